// round 11
// baseline (speedup 1.0000x reference)
#include <cuda_runtime.h>
#include <cuda_fp16.h>
#include <cstdint>
#include <math.h>

#define BATCH 256
#define SEQ   512
#define DIM   1024
#define VOCAB 32003
#define VPAD  32128   // VOCAB padded to 128

// ---------------- scratch ----------------
__device__ float g_gi[BATCH * 3 * DIM];
__device__ float g_h0[BATCH * DIM];
__device__ float g_cat[BATCH * 2 * DIM];
__device__ uint32_t g_Apack[BATCH * (DIM / 2)];
// pre-packed fp16 weights (swizzled gmem layout, row pitch = K/2 words)
__device__ uint32_t g_OutWp[VPAD * (DIM / 2)];
__device__ uint32_t g_Wih0p[3 * DIM * (DIM / 2)];
__device__ uint32_t g_Wih1p[3 * DIM * (DIM / 2)];
__device__ uint32_t g_Prep [DIM * DIM];

__device__ __forceinline__ float celu1(float x) { return x > 0.f ? x : expm1f(x); }

// ---------------- fp16 helpers ----------------
__device__ __forceinline__ uint32_t h2pack(float x, float y) {
    __half2 h = __floats2half2_rn(x, y);
    return *(uint32_t*)&h;
}
__device__ __forceinline__ uint4 packq(float4 x, float4 y) {
    uint4 w;
    w.x = h2pack(x.x, x.y);
    w.y = h2pack(y.x, y.y);
    w.z = h2pack(x.z, x.w);
    w.w = h2pack(y.z, y.w);
    return w;
}
__device__ __forceinline__ void mmaf16(float* c, uint32_t a0, uint32_t a1, uint32_t a2,
                                       uint32_t a3, uint32_t b0, uint32_t b1) {
    asm volatile("mma.sync.aligned.m16n8k16.row.col.f32.f16.f16.f32 "
                 "{%0,%1,%2,%3}, {%4,%5,%6,%7}, {%8,%9}, {%0,%1,%2,%3};"
                 : "+f"(c[0]), "+f"(c[1]), "+f"(c[2]), "+f"(c[3])
                 : "r"(a0), "r"(a1), "r"(a2), "r"(a3), "r"(b0), "r"(b1));
}

// ---------------- cp.async helpers ----------------
#define CP_ASYNC16(dst, src) \
    asm volatile("cp.async.cg.shared.global [%0], [%1], 16;" :: "r"(dst), "l"(src))
#define CP_COMMIT() asm volatile("cp.async.commit_group;" ::: "memory")
#define CP_WAIT1()  asm volatile("cp.async.wait_group 1;" ::: "memory")
#define CP_WAIT2()  asm volatile("cp.async.wait_group 2;" ::: "memory")

#define LP    24
#define PLANE (128 * LP)
#define BUFW  (2 * PLANE)
#define NBUF  4
#define GM_SMEM_BYTES (NBUF * BUFW * 4)   // 98304

// =====================================================================
// prepack_w: fp32 weights [Nsrc, ldw] -> swizzled fp16 rows [Npad, K/2 u32]
// =====================================================================
__global__ void __launch_bounds__(256)
prepack_w(const float* __restrict__ W, int ldw, int Nsrc, int K,
          uint32_t* __restrict__ out)
{
    int idx = blockIdx.x * 256 + threadIdx.x;
    int nch = K / 32;
    int row = idx / nch, ch = idx - row * nch;
    int srow = row < Nsrc ? row : Nsrc - 1;
    const float4* p = (const float4*)(W + (size_t)srow * ldw + ch * 32);
    float4 p0 = p[0], p1 = p[1], p2 = p[2], p3 = p[3];
    float4 p4 = p[4], p5 = p[5], p6 = p[6], p7 = p[7];
    int bp = (row >> 2) & 1;
    uint32_t* o = out + (size_t)row * (K / 2) + ch * 16;
    *(uint4*)(o + 4 * bp)           = packq(p0, p2);
    *(uint4*)(o + 4 * (bp ^ 1))     = packq(p1, p3);
    *(uint4*)(o + 8 + 4 * (bp ^ 1)) = packq(p4, p6);
    *(uint4*)(o + 8 + 4 * bp)       = packq(p5, p7);
}

// =====================================================================
// gemm_f16: C[256, N] = A[256,K] @ Bpack[N,K]^T + bias
// A fp32 converted by producers; B pure cp.async (pre-packed).
// 4-stage ring, wait_group 2. EPI=0: fp32 +bias. EPI=1: celu + pack->Apack.
// =====================================================================
template<int EPI>
__global__ void __launch_bounds__(256)
gemm_f16(int N, int K,
         const float* __restrict__ A, int lda, const int* __restrict__ gather,
         const uint32_t* __restrict__ Bpack,
         const float* __restrict__ bias,
         void* __restrict__ Cout, int ldc)
{
    extern __shared__ uint32_t sm[];
    const uint32_t smb = (uint32_t)__cvta_generic_to_shared(sm);
    const int t    = threadIdx.x;
    const int lane = t & 31;
    const int wid  = t >> 5;
    const int wm   = wid >> 2;
    const int wn   = wid & 3;
    const int bm   = blockIdx.x & 1;
    const int bn   = blockIdx.x >> 1;
    const int NCH  = K / 32;
    const int bpitch = K / 2;

    // ---- producers ----
    const int rb   = t >> 1;
    const int half = t & 1;
    const int bp   = (rb >> 2) & 1;
    const int wq0  = 8 * half + 4 * (bp ^ half);
    const int wq1  = 8 * half + 4 * ((bp ^ 1) ^ half);

    int arow = bm * 128 + rb;
    if (gather) arow = gather[arow];
    const float* asrc = A + (size_t)arow * lda + half * 16;
    const uint32_t* bsrc = Bpack + (size_t)(bn * 128 + rb) * bpitch + half * 8;
    const uint32_t dstOff = (uint32_t)(rb * LP + half * 8) * 4;

    float4 pa[4];
    auto ldA = [&](int ch) {
        const float4* qa = (const float4*)(asrc + ch * 32);
        pa[0] = qa[0]; pa[1] = qa[1]; pa[2] = qa[2]; pa[3] = qa[3];
    };
    auto stA = [&](int buf) {
        uint32_t* ba = sm + buf * BUFW + rb * LP;
        *(uint4*)(ba + wq0) = packq(pa[0], pa[2]);
        *(uint4*)(ba + wq1) = packq(pa[1], pa[3]);
    };
    auto issueB = [&](int ch) {
        int buf = ch & (NBUF - 1);
        uint32_t d = smb + (uint32_t)buf * BUFW * 4 + (uint32_t)PLANE * 4 + dstOff;
        const uint32_t* s = bsrc + ch * 16;
        CP_ASYNC16(d, s);
        CP_ASYNC16(d + 16, s + 4);
    };

    float acc[4][4][4];
#pragma unroll
    for (int i = 0; i < 4; i++)
#pragma unroll
        for (int j = 0; j < 4; j++)
#pragma unroll
            for (int k = 0; k < 4; k++) acc[i][j][k] = 0.f;

    const int c_ = lane & 3;
    const int bt = (lane >> 4) & 1;
    const int q2 = (c_ >> 1) ^ bt;
    const int rA = wm * 64 + (lane >> 2);
    const int cB = wn * 32 + (lane >> 2);

    // prologue
    ldA(0);
    issueB(0); CP_COMMIT();
    issueB(1); CP_COMMIT();
    issueB(2); CP_COMMIT();
    stA(0);
    ldA(1);
    CP_WAIT2();
    __syncthreads();

    for (int ch = 0; ch < NCH; ch++) {
        if (ch + 1 < NCH) stA((ch + 1) & (NBUF - 1));
        if (ch + 2 < NCH) ldA(ch + 2);
        if (ch + 3 < NCH) { issueB(ch + 3); CP_COMMIT(); }
        CP_WAIT2();

        const uint32_t* Ab = sm + (ch & (NBUF - 1)) * BUFW;
        const uint32_t* Bb = Ab + PLANE;
#pragma unroll
        for (int h = 0; h < 2; h++) {
            const int off = 8 * h + 4 * (q2 ^ h) + 2 * (c_ & 1);
            uint2 af[4][2];
#pragma unroll
            for (int mt = 0; mt < 4; mt++) {
                af[mt][0] = *(const uint2*)(Ab + (rA + 16 * mt) * LP + off);
                af[mt][1] = *(const uint2*)(Ab + (rA + 16 * mt + 8) * LP + off);
            }
#pragma unroll
            for (int nt = 0; nt < 4; nt++) {
                uint2 bf = *(const uint2*)(Bb + (cB + 8 * nt) * LP + off);
#pragma unroll
                for (int mt = 0; mt < 4; mt++)
                    mmaf16(acc[mt][nt], af[mt][0].x, af[mt][1].x,
                           af[mt][0].y, af[mt][1].y, bf.x, bf.y);
            }
        }
        __syncthreads();
    }

    // ---- epilogue ----
    const int n0 = bn * 128 + wn * 32 + 2 * c_;
    float bz[8];
#pragma unroll
    for (int nt = 0; nt < 4; nt++) {
        bz[2 * nt]     = bias[n0 + 8 * nt];
        bz[2 * nt + 1] = bias[n0 + 8 * nt + 1];
    }
    const int m0 = bm * 128 + wm * 64 + (lane >> 2);
    if (EPI == 0) {
        float* C = (float*)Cout;
#pragma unroll
        for (int mt = 0; mt < 4; mt++) {
            float* r0 = C + (size_t)(m0 + 16 * mt) * ldc;
            float* r1 = r0 + (size_t)8 * ldc;
#pragma unroll
            for (int nt = 0; nt < 4; nt++) {
                int n = n0 + 8 * nt;
                r0[n]     = acc[mt][nt][0] + bz[2 * nt];
                r0[n + 1] = acc[mt][nt][1] + bz[2 * nt + 1];
                r1[n]     = acc[mt][nt][2] + bz[2 * nt];
                r1[n + 1] = acc[mt][nt][3] + bz[2 * nt + 1];
            }
        }
    } else {
        // celu + pack into g_Apack swizzled layout.
        // For element k=n of row m: word = ch*16 + 8h + 4*((pair>>1)^bp^h)
        //                                + 2*(pair&1) + group, pair=c_, group=qq.
        uint32_t* ap = (uint32_t*)Cout;
        const int bpm = (m0 >> 2) & 1;   // == bt for all written rows
#pragma unroll
        for (int mt = 0; mt < 4; mt++) {
            int r0 = m0 + 16 * mt, r1 = r0 + 8;
#pragma unroll
            for (int nt = 0; nt < 4; nt++) {
                float v0 = celu1(acc[mt][nt][0] + bz[2 * nt]);
                float v1 = celu1(acc[mt][nt][1] + bz[2 * nt + 1]);
                float v2 = celu1(acc[mt][nt][2] + bz[2 * nt]);
                float v3 = celu1(acc[mt][nt][3] + bz[2 * nt + 1]);
                int hh = nt >> 1, qq = nt & 1;
                int w = (bn * 4 + wn) * 16 + 8 * hh
                      + 4 * ((c_ >> 1) ^ bpm ^ hh) + 2 * (c_ & 1) + qq;
                ap[(size_t)r0 * (DIM / 2) + w] = h2pack(v0, v1);
                ap[(size_t)r1 * (DIM / 2) + w] = h2pack(v2, v3);
            }
        }
    }
}

// =====================================================================
// Logits GEMM: pure cp.async (A from g_Apack, B from g_OutWp), 4-stage.
// =====================================================================
__global__ void __launch_bounds__(256, 2)
logits_f16(const uint32_t* __restrict__ Apack, const uint32_t* __restrict__ Bpack,
           const float* __restrict__ bias, float* __restrict__ C)
{
    extern __shared__ uint32_t sm[];
    const uint32_t smb = (uint32_t)__cvta_generic_to_shared(sm);
    const int t    = threadIdx.x;
    const int lane = t & 31;
    const int wid  = t >> 5;
    const int wm   = wid >> 2;
    const int wn   = wid & 3;
    const int bm   = blockIdx.x & 1;
    const int bn   = blockIdx.x >> 1;

    const int rb   = t >> 1;
    const int half = t & 1;
    const uint32_t* srcA = Apack + (size_t)(bm * 128 + rb) * (DIM / 2) + half * 8;
    const uint32_t* srcB = Bpack + (size_t)(bn * 128 + rb) * (DIM / 2) + half * 8;
    const uint32_t dstOff = (uint32_t)(rb * LP + half * 8) * 4;

    auto issueAB = [&](int ch) {
        int buf = ch & (NBUF - 1);
        uint32_t dA = smb + (uint32_t)buf * BUFW * 4 + dstOff;
        const uint32_t* sA = srcA + ch * 16;
        CP_ASYNC16(dA, sA);
        CP_ASYNC16(dA + 16, sA + 4);
        uint32_t dB = dA + (uint32_t)PLANE * 4;
        const uint32_t* sB = srcB + ch * 16;
        CP_ASYNC16(dB, sB);
        CP_ASYNC16(dB + 16, sB + 4);
    };

    float acc[4][4][4];
#pragma unroll
    for (int i = 0; i < 4; i++)
#pragma unroll
        for (int j = 0; j < 4; j++)
#pragma unroll
            for (int k = 0; k < 4; k++) acc[i][j][k] = 0.f;

    const int c_ = lane & 3;
    const int bt = (lane >> 4) & 1;
    const int q2 = (c_ >> 1) ^ bt;
    const int rA = wm * 64 + (lane >> 2);
    const int cB = wn * 32 + (lane >> 2);

    issueAB(0); CP_COMMIT();
    issueAB(1); CP_COMMIT();
    issueAB(2); CP_COMMIT();
    CP_WAIT2();
    __syncthreads();

    const int NCHUNK = DIM / 32;
    for (int ch = 0; ch < NCHUNK; ch++) {
        if (ch + 3 < NCHUNK) { issueAB(ch + 3); CP_COMMIT(); }
        CP_WAIT2();

        const uint32_t* Ab = sm + (ch & (NBUF - 1)) * BUFW;
        const uint32_t* Bb = Ab + PLANE;
#pragma unroll
        for (int h = 0; h < 2; h++) {
            const int off = 8 * h + 4 * (q2 ^ h) + 2 * (c_ & 1);
            uint2 af[4][2];
#pragma unroll
            for (int mt = 0; mt < 4; mt++) {
                af[mt][0] = *(const uint2*)(Ab + (rA + 16 * mt) * LP + off);
                af[mt][1] = *(const uint2*)(Ab + (rA + 16 * mt + 8) * LP + off);
            }
#pragma unroll
            for (int nt = 0; nt < 4; nt++) {
                uint2 bf = *(const uint2*)(Bb + (cB + 8 * nt) * LP + off);
#pragma unroll
                for (int mt = 0; mt < 4; mt++)
                    mmaf16(acc[mt][nt], af[mt][0].x, af[mt][1].x,
                           af[mt][0].y, af[mt][1].y, bf.x, bf.y);
            }
        }
        __syncthreads();
    }

    const int n0 = bn * 128 + wn * 32 + 2 * c_;
    float bz[8];
#pragma unroll
    for (int nt = 0; nt < 4; nt++) {
        int n = n0 + 8 * nt;
        bz[2 * nt]     = (n     < VOCAB) ? bias[n]     : 0.f;
        bz[2 * nt + 1] = (n + 1 < VOCAB) ? bias[n + 1] : 0.f;
    }
    const int m0 = bm * 128 + wm * 64 + (lane >> 2);
#pragma unroll
    for (int mt = 0; mt < 4; mt++) {
        float* r0 = C + (size_t)(m0 + 16 * mt) * VOCAB;
        float* r1 = r0 + (size_t)8 * VOCAB;
#pragma unroll
        for (int nt = 0; nt < 4; nt++) {
            int n = n0 + 8 * nt;
            if (n < VOCAB) {
                r0[n] = acc[mt][nt][0] + bz[2 * nt];
                r1[n] = acc[mt][nt][2] + bz[2 * nt];
            }
            if (n + 1 < VOCAB) {
                r0[n + 1] = acc[mt][nt][1] + bz[2 * nt + 1];
                r1[n + 1] = acc[mt][nt][3] + bz[2 * nt + 1];
            }
        }
    }
}

// =====================================================================
// GRU gates (zero previous hidden state): h' = (1-z) * n   (layer 0)
// =====================================================================
__global__ void gru_gates(const float* __restrict__ gi, const float* __restrict__ bhh,
                          float* __restrict__ h, int ldh)
{
    int idx = blockIdx.x * blockDim.x + threadIdx.x;
    int b = idx >> 10, d = idx & 1023;
    const float* g = gi + (size_t)b * (3 * DIM);
    float r = 1.f / (1.f + expf(-(g[d]           + bhh[d])));
    float z = 1.f / (1.f + expf(-(g[DIM + d]     + bhh[DIM + d])));
    float n = tanhf(g[2 * DIM + d] + r * bhh[2 * DIM + d]);
    h[(size_t)b * ldh + d] = (1.f - z) * n;
}

// =====================================================================
// Fused attention (unchanged): h1 gates in-block + online softmax.
// =====================================================================
#define ATTN_SMEM_BYTES ((1024 + 2 * 8 * 1024 + 8 + 512) * 4)

__global__ void __launch_bounds__(256)
attn_kernel(const float* __restrict__ enc, const int* __restrict__ mask,
            const float* __restrict__ gi, const float* __restrict__ bhh,
            float* __restrict__ cat)
{
    extern __shared__ float smf[];
    float* h1s   = smf;
    float* tiles = smf + 1024;
    float* wsh   = smf + 1024 + 16384;
    int*   msk   = (int*)(smf + 1024 + 16384 + 8);

    const int b   = blockIdx.x;
    const int tid = threadIdx.x;
    const float* encb  = enc  + (size_t)b * SEQ * DIM;
    const int*   maskb = mask + b * SEQ;

    msk[tid]       = maskb[tid];
    msk[tid + 256] = maskb[tid + 256];

    {
        const float* g = gi + (size_t)b * (3 * DIM);
        int d = tid * 4;
        float4 vr = *(const float4*)(g + d);
        float4 vz = *(const float4*)(g + DIM + d);
        float4 vn = *(const float4*)(g + 2 * DIM + d);
        float4 br = *(const float4*)(bhh + d);
        float4 bz = *(const float4*)(bhh + DIM + d);
        float4 bn = *(const float4*)(bhh + 2 * DIM + d);
        float h[4];
        float r0 = 1.f / (1.f + expf(-(vr.x + br.x)));
        float z0 = 1.f / (1.f + expf(-(vz.x + bz.x)));
        h[0] = (1.f - z0) * tanhf(vn.x + r0 * bn.x);
        float r1 = 1.f / (1.f + expf(-(vr.y + br.y)));
        float z1 = 1.f / (1.f + expf(-(vz.y + bz.y)));
        h[1] = (1.f - z1) * tanhf(vn.y + r1 * bn.y);
        float r2 = 1.f / (1.f + expf(-(vr.z + br.z)));
        float z2 = 1.f / (1.f + expf(-(vz.z + bz.z)));
        h[2] = (1.f - z2) * tanhf(vn.z + r2 * bn.z);
        float r3 = 1.f / (1.f + expf(-(vr.w + br.w)));
        float z3 = 1.f / (1.f + expf(-(vz.w + bz.w)));
        h[3] = (1.f - z3) * tanhf(vn.w + r3 * bn.w);
        float4 hv = make_float4(h[0], h[1], h[2], h[3]);
        *(float4*)(h1s + d) = hv;
        *(float4*)(cat + (size_t)b * (2 * DIM) + d) = hv;
    }

    const uint32_t tbase = (uint32_t)__cvta_generic_to_shared(tiles);
    auto issue = [&](int it) {
        const float* src = encb + (size_t)it * 8 * DIM + tid * 4;
        uint32_t dst = tbase + (uint32_t)((it & 1) * 32768 + tid * 16);
#pragma unroll
        for (int i = 0; i < 8; i++)
            CP_ASYNC16(dst + i * 4096, (const void*)(src + i * 1024));
    };

    issue(0); CP_COMMIT();
    issue(1); CP_COMMIT();

    float m = -1e30f, l = 0.f;
    float4 acc = make_float4(0.f, 0.f, 0.f, 0.f);

    for (int it = 0; it < SEQ / 8; it++) {
        CP_WAIT1();
        __syncthreads();
        const float* tb = tiles + (it & 1) * 8192;

        {
            int w = tid >> 5, lane = tid & 31;
            float p = 0.f;
            const float4* er = (const float4*)(tb + w * 1024);
            const float4* hr = (const float4*)h1s;
#pragma unroll
            for (int i = 0; i < 8; i++) {
                float4 e  = er[lane + i * 32];
                float4 hv = hr[lane + i * 32];
                p += e.x * hv.x + e.y * hv.y + e.z * hv.z + e.w * hv.w;
            }
#pragma unroll
            for (int off = 16; off; off >>= 1) p += __shfl_xor_sync(0xffffffffu, p, off);
            if (lane == 0) wsh[w] = msk[it * 8 + w] ? p : -1e30f;
        }
        __syncthreads();

        float wv[8];
        float tm = -1e30f;
#pragma unroll
        for (int j = 0; j < 8; j++) { wv[j] = wsh[j]; tm = fmaxf(tm, wv[j]); }
        float mnew  = fmaxf(m, tm);
        float scale = __expf(m - mnew);
        l *= scale;
        acc.x *= scale; acc.y *= scale; acc.z *= scale; acc.w *= scale;
#pragma unroll
        for (int j = 0; j < 8; j++) {
            float pj = __expf(wv[j] - mnew);
            l += pj;
            float4 e = *(const float4*)(tb + j * 1024 + tid * 4);
            acc.x += pj * e.x; acc.y += pj * e.y; acc.z += pj * e.z; acc.w += pj * e.w;
        }
        m = mnew;
        __syncthreads();

        if (it + 2 < SEQ / 8) issue(it + 2);
        CP_COMMIT();
    }

    float inv = 1.f / l;
    float4 o = make_float4(acc.x * inv, acc.y * inv, acc.z * inv, acc.w * inv);
    *(float4*)(cat + (size_t)b * (2 * DIM) + DIM + tid * 4) = o;
}

// =====================================================================
// launcher
// =====================================================================
extern "C" void kernel_launch(void* const* d_in, const int* in_sizes, int n_in,
                              void* d_out, int out_size)
{
    (void)in_sizes; (void)n_in; (void)out_size;
    const int*   tokens   = (const int*)  d_in[0];
    const float* enc      = (const float*)d_in[1];
    const int*   encmask  = (const int*)  d_in[2];
    const float* dec_emb  = (const float*)d_in[3];
    const float* Wih0     = (const float*)d_in[4];
    const float* bih0     = (const float*)d_in[6];
    const float* bhh0     = (const float*)d_in[7];
    const float* Wih1     = (const float*)d_in[8];
    const float* bih1     = (const float*)d_in[10];
    const float* bhh1     = (const float*)d_in[11];
    const float* preout_w = (const float*)d_in[12];
    const float* preout_b = (const float*)d_in[13];
    const float* out_w    = (const float*)d_in[14];
    const float* out_b    = (const float*)d_in[15];
    float* logits = (float*)d_out;

    float *gi, *h0, *cat;
    uint32_t *apack, *outwp, *w0p, *w1p, *prep;
    cudaGetSymbolAddress((void**)&gi,    g_gi);
    cudaGetSymbolAddress((void**)&h0,    g_h0);
    cudaGetSymbolAddress((void**)&cat,   g_cat);
    cudaGetSymbolAddress((void**)&apack, g_Apack);
    cudaGetSymbolAddress((void**)&outwp, g_OutWp);
    cudaGetSymbolAddress((void**)&w0p,   g_Wih0p);
    cudaGetSymbolAddress((void**)&w1p,   g_Wih1p);
    cudaGetSymbolAddress((void**)&prep,  g_Prep);

    static int smem_set = 0;
    if (!smem_set) {
        cudaFuncSetAttribute(logits_f16, cudaFuncAttributeMaxDynamicSharedMemorySize, GM_SMEM_BYTES);
        cudaFuncSetAttribute(gemm_f16<0>, cudaFuncAttributeMaxDynamicSharedMemorySize, GM_SMEM_BYTES);
        cudaFuncSetAttribute(gemm_f16<1>, cudaFuncAttributeMaxDynamicSharedMemorySize, GM_SMEM_BYTES);
        cudaFuncSetAttribute(attn_kernel, cudaFuncAttributeMaxDynamicSharedMemorySize, ATTN_SMEM_BYTES);
        smem_set = 1;
    }

    // 0) weight prepacks (no deps)
    prepack_w<<<(3 * DIM * 32) / 256, 256>>>(Wih0, 2 * DIM, 3 * DIM, DIM, w0p);
    prepack_w<<<(3 * DIM * 32) / 256, 256>>>(Wih1, DIM, 3 * DIM, DIM, w1p);
    prepack_w<<<(DIM * 64) / 256, 256>>>(preout_w, 2 * DIM, DIM, 2 * DIM, prep);
    prepack_w<<<(VPAD * 32) / 256, 256>>>(out_w, DIM, VOCAB, DIM, outwp);

    // 1) gi0 = dec_emb[tokens] @ Wih0[:, :D]^T + bih0
    gemm_f16<0><<<2 * (3 * DIM / 128), 256, GM_SMEM_BYTES>>>(
        3 * DIM, DIM, dec_emb, DIM, tokens, w0p, bih0, gi, 3 * DIM);

    // 2) h0
    gru_gates<<<(BATCH * DIM) / 256, 256>>>(gi, bhh0, h0, DIM);

    // 3) gi1 = h0 @ Wih1^T + bih1
    gemm_f16<0><<<2 * (3 * DIM / 128), 256, GM_SMEM_BYTES>>>(
        3 * DIM, DIM, h0, DIM, nullptr, w1p, bih1, gi, 3 * DIM);

    // 4) fused: h1 gates + attention summary -> cat
    attn_kernel<<<BATCH, 256, ATTN_SMEM_BYTES>>>(enc, encmask, gi, bhh1, cat);

    // 5) preout: celu + direct fp16-pack into g_Apack
    gemm_f16<1><<<2 * (DIM / 128), 256, GM_SMEM_BYTES>>>(
        DIM, 2 * DIM, cat, 2 * DIM, nullptr, prep, preout_b, apack, 0);

    // 6) logits = Apack @ OutWp^T + out_b   (pure cp.async fp16 MMA)
    logits_f16<<<(VPAD / 128) * 2, 256, GM_SMEM_BYTES>>>(apack, outwp, out_b, logits);
}

// round 12
// speedup vs baseline: 1.1081x; 1.1081x over previous
#include <cuda_runtime.h>
#include <cuda_fp16.h>
#include <cstdint>
#include <math.h>

#define BATCH 256
#define SEQ   512
#define DIM   1024
#define VOCAB 32003
#define VPAD  32128   // VOCAB padded to 128

// ---------------- scratch ----------------
__device__ float g_gi[BATCH * 3 * DIM];
__device__ float g_h0[BATCH * DIM];
__device__ float g_cat[BATCH * 2 * DIM];
__device__ uint32_t g_Apack[BATCH * (DIM / 2)];
// pre-packed fp16 weights for the small GEMMs
__device__ uint32_t g_Wih0p[3 * DIM * (DIM / 2)];
__device__ uint32_t g_Wih1p[3 * DIM * (DIM / 2)];
__device__ uint32_t g_Prep [DIM * DIM];

__device__ __forceinline__ float celu1(float x) { return x > 0.f ? x : expm1f(x); }

// ---------------- fp16 helpers ----------------
__device__ __forceinline__ uint32_t h2pack(float x, float y) {
    __half2 h = __floats2half2_rn(x, y);
    return *(uint32_t*)&h;
}
__device__ __forceinline__ uint4 packq(float4 x, float4 y) {
    uint4 w;
    w.x = h2pack(x.x, x.y);
    w.y = h2pack(y.x, y.y);
    w.z = h2pack(x.z, x.w);
    w.w = h2pack(y.z, y.w);
    return w;
}
__device__ __forceinline__ void mmaf16(float* c, uint32_t a0, uint32_t a1, uint32_t a2,
                                       uint32_t a3, uint32_t b0, uint32_t b1) {
    asm volatile("mma.sync.aligned.m16n8k16.row.col.f32.f16.f16.f32 "
                 "{%0,%1,%2,%3}, {%4,%5,%6,%7}, {%8,%9}, {%0,%1,%2,%3};"
                 : "+f"(c[0]), "+f"(c[1]), "+f"(c[2]), "+f"(c[3])
                 : "r"(a0), "r"(a1), "r"(a2), "r"(a3), "r"(b0), "r"(b1));
}

// ---------------- cp.async helpers ----------------
#define CP_ASYNC16(dst, src) \
    asm volatile("cp.async.cg.shared.global [%0], [%1], 16;" :: "r"(dst), "l"(src))
#define CP_COMMIT() asm volatile("cp.async.commit_group;" ::: "memory")
#define CP_WAIT1()  asm volatile("cp.async.wait_group 1;" ::: "memory")
#define CP_WAIT2()  asm volatile("cp.async.wait_group 2;" ::: "memory")

#define LP    24
#define PLANE (128 * LP)
#define BUFW  (2 * PLANE)
#define NBUF  4
#define GM_SMEM_BYTES (NBUF * BUFW * 4)   // 98304 (small GEMMs)

// logits256 geometry: A plane 256 rows + B plane 128 rows, 3 buffers
#define APLANE256 (256 * LP)
#define BUFW256   (APLANE256 + PLANE)     // 9216 words
#define LG256_SMEM_BYTES (3 * BUFW256 * 4)  // 110592

// =====================================================================
// prepack_w: fp32 weights [Nsrc, ldw] -> swizzled fp16 rows [N, K/2 u32]
// (small GEMM weights only)
// =====================================================================
__global__ void __launch_bounds__(256)
prepack_w(const float* __restrict__ W, int ldw, int Nsrc, int K,
          uint32_t* __restrict__ out)
{
    int idx = blockIdx.x * 256 + threadIdx.x;
    int nch = K / 32;
    int row = idx / nch, ch = idx - row * nch;
    int srow = row < Nsrc ? row : Nsrc - 1;
    const float4* p = (const float4*)(W + (size_t)srow * ldw + ch * 32);
    float4 p0 = p[0], p1 = p[1], p2 = p[2], p3 = p[3];
    float4 p4 = p[4], p5 = p[5], p6 = p[6], p7 = p[7];
    int bp = (row >> 2) & 1;
    uint32_t* o = out + (size_t)row * (K / 2) + ch * 16;
    *(uint4*)(o + 4 * bp)           = packq(p0, p2);
    *(uint4*)(o + 4 * (bp ^ 1))     = packq(p1, p3);
    *(uint4*)(o + 8 + 4 * (bp ^ 1)) = packq(p4, p6);
    *(uint4*)(o + 8 + 4 * bp)       = packq(p5, p7);
}

// =====================================================================
// gemm_f16 (small GEMMs, unchanged from R11): C = A @ Bpack^T + bias
// EPI=0: fp32 store. EPI=1: celu + pack -> g_Apack layout.
// =====================================================================
template<int EPI>
__global__ void __launch_bounds__(256)
gemm_f16(int N, int K,
         const float* __restrict__ A, int lda, const int* __restrict__ gather,
         const uint32_t* __restrict__ Bpack,
         const float* __restrict__ bias,
         void* __restrict__ Cout, int ldc)
{
    extern __shared__ uint32_t sm[];
    const uint32_t smb = (uint32_t)__cvta_generic_to_shared(sm);
    const int t    = threadIdx.x;
    const int lane = t & 31;
    const int wid  = t >> 5;
    const int wm   = wid >> 2;
    const int wn   = wid & 3;
    const int bm   = blockIdx.x & 1;
    const int bn   = blockIdx.x >> 1;
    const int NCH  = K / 32;
    const int bpitch = K / 2;

    const int rb   = t >> 1;
    const int half = t & 1;
    const int bp   = (rb >> 2) & 1;
    const int wq0  = 8 * half + 4 * (bp ^ half);
    const int wq1  = 8 * half + 4 * ((bp ^ 1) ^ half);

    int arow = bm * 128 + rb;
    if (gather) arow = gather[arow];
    const float* asrc = A + (size_t)arow * lda + half * 16;
    const uint32_t* bsrc = Bpack + (size_t)(bn * 128 + rb) * bpitch + half * 8;
    const uint32_t dstOff = (uint32_t)(rb * LP + half * 8) * 4;

    float4 pa[4];
    auto ldA = [&](int ch) {
        const float4* qa = (const float4*)(asrc + ch * 32);
        pa[0] = qa[0]; pa[1] = qa[1]; pa[2] = qa[2]; pa[3] = qa[3];
    };
    auto stA = [&](int buf) {
        uint32_t* ba = sm + buf * BUFW + rb * LP;
        *(uint4*)(ba + wq0) = packq(pa[0], pa[2]);
        *(uint4*)(ba + wq1) = packq(pa[1], pa[3]);
    };
    auto issueB = [&](int ch) {
        int buf = ch & (NBUF - 1);
        uint32_t d = smb + (uint32_t)buf * BUFW * 4 + (uint32_t)PLANE * 4 + dstOff;
        const uint32_t* s = bsrc + ch * 16;
        CP_ASYNC16(d, s);
        CP_ASYNC16(d + 16, s + 4);
    };

    float acc[4][4][4];
#pragma unroll
    for (int i = 0; i < 4; i++)
#pragma unroll
        for (int j = 0; j < 4; j++)
#pragma unroll
            for (int k = 0; k < 4; k++) acc[i][j][k] = 0.f;

    const int c_ = lane & 3;
    const int bt = (lane >> 4) & 1;
    const int q2 = (c_ >> 1) ^ bt;
    const int rA = wm * 64 + (lane >> 2);
    const int cB = wn * 32 + (lane >> 2);

    ldA(0);
    issueB(0); CP_COMMIT();
    issueB(1); CP_COMMIT();
    issueB(2); CP_COMMIT();
    stA(0);
    ldA(1);
    CP_WAIT2();
    __syncthreads();

    for (int ch = 0; ch < NCH; ch++) {
        if (ch + 1 < NCH) stA((ch + 1) & (NBUF - 1));
        if (ch + 2 < NCH) ldA(ch + 2);
        if (ch + 3 < NCH) { issueB(ch + 3); CP_COMMIT(); }
        CP_WAIT2();

        const uint32_t* Ab = sm + (ch & (NBUF - 1)) * BUFW;
        const uint32_t* Bb = Ab + PLANE;
#pragma unroll
        for (int h = 0; h < 2; h++) {
            const int off = 8 * h + 4 * (q2 ^ h) + 2 * (c_ & 1);
            uint2 af[4][2];
#pragma unroll
            for (int mt = 0; mt < 4; mt++) {
                af[mt][0] = *(const uint2*)(Ab + (rA + 16 * mt) * LP + off);
                af[mt][1] = *(const uint2*)(Ab + (rA + 16 * mt + 8) * LP + off);
            }
#pragma unroll
            for (int nt = 0; nt < 4; nt++) {
                uint2 bf = *(const uint2*)(Bb + (cB + 8 * nt) * LP + off);
#pragma unroll
                for (int mt = 0; mt < 4; mt++)
                    mmaf16(acc[mt][nt], af[mt][0].x, af[mt][1].x,
                           af[mt][0].y, af[mt][1].y, bf.x, bf.y);
            }
        }
        __syncthreads();
    }

    const int n0 = bn * 128 + wn * 32 + 2 * c_;
    float bz[8];
#pragma unroll
    for (int nt = 0; nt < 4; nt++) {
        bz[2 * nt]     = bias[n0 + 8 * nt];
        bz[2 * nt + 1] = bias[n0 + 8 * nt + 1];
    }
    const int m0 = bm * 128 + wm * 64 + (lane >> 2);
    if (EPI == 0) {
        float* C = (float*)Cout;
#pragma unroll
        for (int mt = 0; mt < 4; mt++) {
            float* r0 = C + (size_t)(m0 + 16 * mt) * ldc;
            float* r1 = r0 + (size_t)8 * ldc;
#pragma unroll
            for (int nt = 0; nt < 4; nt++) {
                int n = n0 + 8 * nt;
                r0[n]     = acc[mt][nt][0] + bz[2 * nt];
                r0[n + 1] = acc[mt][nt][1] + bz[2 * nt + 1];
                r1[n]     = acc[mt][nt][2] + bz[2 * nt];
                r1[n + 1] = acc[mt][nt][3] + bz[2 * nt + 1];
            }
        }
    } else {
        uint32_t* ap = (uint32_t*)Cout;
        const int bpm = (m0 >> 2) & 1;
#pragma unroll
        for (int mt = 0; mt < 4; mt++) {
            int r0 = m0 + 16 * mt, r1 = r0 + 8;
#pragma unroll
            for (int nt = 0; nt < 4; nt++) {
                float v0 = celu1(acc[mt][nt][0] + bz[2 * nt]);
                float v1 = celu1(acc[mt][nt][1] + bz[2 * nt + 1]);
                float v2 = celu1(acc[mt][nt][2] + bz[2 * nt]);
                float v3 = celu1(acc[mt][nt][3] + bz[2 * nt + 1]);
                int hh = nt >> 1, qq = nt & 1;
                int w = (bn * 4 + wn) * 16 + 8 * hh
                      + 4 * ((c_ >> 1) ^ bpm ^ hh) + 2 * (c_ & 1) + qq;
                ap[(size_t)r0 * (DIM / 2) + w] = h2pack(v0, v1);
                ap[(size_t)r1 * (DIM / 2) + w] = h2pack(v2, v3);
            }
        }
    }
}

// =====================================================================
// logits256: C[256, 32003] = Apack[256,1024] @ out_w[32003,1024]^T + bias
// CTA tile 256x128 (M = full batch), 8 warps of 64x64, grid = VPAD/128.
// A plane (256 rows) pure cp.async from g_Apack; B converted in-kernel
// (each B row used by exactly one CTA). NBUF=3 ring, 1 sync/chunk.
// =====================================================================
__global__ void __launch_bounds__(256, 1)
logits256(const uint32_t* __restrict__ Apack, const float* __restrict__ Bw,
          const float* __restrict__ bias, float* __restrict__ C)
{
    extern __shared__ uint32_t sm[];
    const uint32_t smb = (uint32_t)__cvta_generic_to_shared(sm);
    const int t    = threadIdx.x;
    const int lane = t & 31;
    const int wid  = t >> 5;
    const int wm   = wid & 3;        // m block 0..3 (64 rows each)
    const int wn   = wid >> 2;       // n block 0..1 (64 cols each)
    const int bn   = blockIdx.x;

    // ---- producers ----
    const int rb   = t >> 1;
    const int half = t & 1;
    const int bpB  = (rb >> 2) & 1;
    const int wq0  = 8 * half + 4 * (bpB ^ half);
    const int wq1  = 8 * half + 4 * ((bpB ^ 1) ^ half);

    int ng = bn * 128 + rb;
    if (ng > VOCAB - 1) ng = VOCAB - 1;
    const float* bsrc = Bw + (size_t)ng * DIM + half * 16;
    const uint32_t* srcA0 = Apack + (size_t)rb * (DIM / 2) + half * 8;
    const uint32_t* srcA1 = Apack + (size_t)(rb + 128) * (DIM / 2) + half * 8;
    const uint32_t dstA0 = (uint32_t)(rb * LP + half * 8) * 4;
    const uint32_t dstA1 = (uint32_t)((rb + 128) * LP + half * 8) * 4;

    float4 pf[4];
    auto ldB = [&](int ch) {
        const float4* p = (const float4*)(bsrc + ch * 32);
        pf[0] = p[0]; pf[1] = p[1]; pf[2] = p[2]; pf[3] = p[3];
    };
    auto stB = [&](int buf) {
        uint32_t* base = sm + buf * BUFW256 + APLANE256 + rb * LP;
        *(uint4*)(base + wq0) = packq(pf[0], pf[2]);
        *(uint4*)(base + wq1) = packq(pf[1], pf[3]);
    };
    auto issueA = [&](int ch, int buf) {
        uint32_t d = smb + (uint32_t)buf * BUFW256 * 4;
        const uint32_t* s0 = srcA0 + ch * 16;
        const uint32_t* s1 = srcA1 + ch * 16;
        CP_ASYNC16(d + dstA0, s0);
        CP_ASYNC16(d + dstA0 + 16, s0 + 4);
        CP_ASYNC16(d + dstA1, s1);
        CP_ASYNC16(d + dstA1 + 16, s1 + 4);
        CP_COMMIT();
    };

    float acc[4][8][4];
#pragma unroll
    for (int i = 0; i < 4; i++)
#pragma unroll
        for (int j = 0; j < 8; j++)
#pragma unroll
            for (int k = 0; k < 4; k++) acc[i][j][k] = 0.f;

    const int c_ = lane & 3;
    const int bt = (lane >> 4) & 1;
    const int q2 = (c_ >> 1) ^ bt;
    const int rA = wm * 64 + (lane >> 2);
    const int cB = wn * 64 + (lane >> 2);

    // prologue
    ldB(0);
    issueA(0, 0);
    issueA(1, 1);
    stB(0);
    ldB(1);
    CP_WAIT1();        // A0 complete (A1 outstanding)
    __syncthreads();   // publish A0 + B0

    const int NCH = DIM / 32;   // 32
    int bufC = 0;               // buffer of chunk ch
    for (int ch = 0; ch < NCH; ch++) {
        const int bufN  = bufC + 1 == 3 ? 0 : bufC + 1;   // (ch+1)%3
        const int bufNN = bufN + 1 == 3 ? 0 : bufN + 1;   // (ch+2)%3
        if (ch + 1 < NCH) stB(bufN);
        if (ch + 2 < NCH) ldB(ch + 2);
        if (ch + 2 < NCH) issueA(ch + 2, bufNN);

        const uint32_t* Ab = sm + bufC * BUFW256;
        const uint32_t* Bb = Ab + APLANE256;
#pragma unroll
        for (int h = 0; h < 2; h++) {
            const int off = 8 * h + 4 * (q2 ^ h) + 2 * (c_ & 1);
            uint2 af[4][2];
#pragma unroll
            for (int mt = 0; mt < 4; mt++) {
                af[mt][0] = *(const uint2*)(Ab + (rA + 16 * mt) * LP + off);
                af[mt][1] = *(const uint2*)(Ab + (rA + 16 * mt + 8) * LP + off);
            }
#pragma unroll
            for (int nt = 0; nt < 8; nt++) {
                uint2 bf = *(const uint2*)(Bb + (cB + 8 * nt) * LP + off);
#pragma unroll
                for (int mt = 0; mt < 4; mt++)
                    mmaf16(acc[mt][nt], af[mt][0].x, af[mt][1].x,
                           af[mt][0].y, af[mt][1].y, bf.x, bf.y);
            }
        }
        CP_WAIT1();        // A(ch+1) complete (issued a full iter ago)
        __syncthreads();   // publish A(ch+1) + B(ch+1)
        bufC = bufN;
    }

    // ---- epilogue: guarded scalar stores ----
    const int n0 = bn * 128 + wn * 64 + 2 * c_;
    float bz[16];
#pragma unroll
    for (int nt = 0; nt < 8; nt++) {
        int n = n0 + 8 * nt;
        bz[2 * nt]     = (n     < VOCAB) ? bias[n]     : 0.f;
        bz[2 * nt + 1] = (n + 1 < VOCAB) ? bias[n + 1] : 0.f;
    }
    const int m0 = wm * 64 + (lane >> 2);
#pragma unroll
    for (int mt = 0; mt < 4; mt++) {
        float* r0 = C + (size_t)(m0 + 16 * mt) * VOCAB;
        float* r1 = r0 + (size_t)8 * VOCAB;
#pragma unroll
        for (int nt = 0; nt < 8; nt++) {
            int n = n0 + 8 * nt;
            if (n < VOCAB) {
                r0[n] = acc[mt][nt][0] + bz[2 * nt];
                r1[n] = acc[mt][nt][2] + bz[2 * nt];
            }
            if (n + 1 < VOCAB) {
                r0[n + 1] = acc[mt][nt][1] + bz[2 * nt + 1];
                r1[n + 1] = acc[mt][nt][3] + bz[2 * nt + 1];
            }
        }
    }
}

// =====================================================================
// GRU gates (zero previous hidden state): h' = (1-z) * n   (layer 0)
// =====================================================================
__global__ void gru_gates(const float* __restrict__ gi, const float* __restrict__ bhh,
                          float* __restrict__ h, int ldh)
{
    int idx = blockIdx.x * blockDim.x + threadIdx.x;
    int b = idx >> 10, d = idx & 1023;
    const float* g = gi + (size_t)b * (3 * DIM);
    float r = 1.f / (1.f + expf(-(g[d]           + bhh[d])));
    float z = 1.f / (1.f + expf(-(g[DIM + d]     + bhh[DIM + d])));
    float n = tanhf(g[2 * DIM + d] + r * bhh[2 * DIM + d]);
    h[(size_t)b * ldh + d] = (1.f - z) * n;
}

// =====================================================================
// Fused attention (unchanged): h1 gates in-block + online softmax.
// =====================================================================
#define ATTN_SMEM_BYTES ((1024 + 2 * 8 * 1024 + 8 + 512) * 4)

__global__ void __launch_bounds__(256)
attn_kernel(const float* __restrict__ enc, const int* __restrict__ mask,
            const float* __restrict__ gi, const float* __restrict__ bhh,
            float* __restrict__ cat)
{
    extern __shared__ float smf[];
    float* h1s   = smf;
    float* tiles = smf + 1024;
    float* wsh   = smf + 1024 + 16384;
    int*   msk   = (int*)(smf + 1024 + 16384 + 8);

    const int b   = blockIdx.x;
    const int tid = threadIdx.x;
    const float* encb  = enc  + (size_t)b * SEQ * DIM;
    const int*   maskb = mask + b * SEQ;

    msk[tid]       = maskb[tid];
    msk[tid + 256] = maskb[tid + 256];

    {
        const float* g = gi + (size_t)b * (3 * DIM);
        int d = tid * 4;
        float4 vr = *(const float4*)(g + d);
        float4 vz = *(const float4*)(g + DIM + d);
        float4 vn = *(const float4*)(g + 2 * DIM + d);
        float4 br = *(const float4*)(bhh + d);
        float4 bz = *(const float4*)(bhh + DIM + d);
        float4 bn = *(const float4*)(bhh + 2 * DIM + d);
        float h[4];
        float r0 = 1.f / (1.f + expf(-(vr.x + br.x)));
        float z0 = 1.f / (1.f + expf(-(vz.x + bz.x)));
        h[0] = (1.f - z0) * tanhf(vn.x + r0 * bn.x);
        float r1 = 1.f / (1.f + expf(-(vr.y + br.y)));
        float z1 = 1.f / (1.f + expf(-(vz.y + bz.y)));
        h[1] = (1.f - z1) * tanhf(vn.y + r1 * bn.y);
        float r2 = 1.f / (1.f + expf(-(vr.z + br.z)));
        float z2 = 1.f / (1.f + expf(-(vz.z + bz.z)));
        h[2] = (1.f - z2) * tanhf(vn.z + r2 * bn.z);
        float r3 = 1.f / (1.f + expf(-(vr.w + br.w)));
        float z3 = 1.f / (1.f + expf(-(vz.w + bz.w)));
        h[3] = (1.f - z3) * tanhf(vn.w + r3 * bn.w);
        float4 hv = make_float4(h[0], h[1], h[2], h[3]);
        *(float4*)(h1s + d) = hv;
        *(float4*)(cat + (size_t)b * (2 * DIM) + d) = hv;
    }

    const uint32_t tbase = (uint32_t)__cvta_generic_to_shared(tiles);
    auto issue = [&](int it) {
        const float* src = encb + (size_t)it * 8 * DIM + tid * 4;
        uint32_t dst = tbase + (uint32_t)((it & 1) * 32768 + tid * 16);
#pragma unroll
        for (int i = 0; i < 8; i++)
            CP_ASYNC16(dst + i * 4096, (const void*)(src + i * 1024));
    };

    issue(0); CP_COMMIT();
    issue(1); CP_COMMIT();

    float m = -1e30f, l = 0.f;
    float4 acc = make_float4(0.f, 0.f, 0.f, 0.f);

    for (int it = 0; it < SEQ / 8; it++) {
        CP_WAIT1();
        __syncthreads();
        const float* tb = tiles + (it & 1) * 8192;

        {
            int w = tid >> 5, lane = tid & 31;
            float p = 0.f;
            const float4* er = (const float4*)(tb + w * 1024);
            const float4* hr = (const float4*)h1s;
#pragma unroll
            for (int i = 0; i < 8; i++) {
                float4 e  = er[lane + i * 32];
                float4 hv = hr[lane + i * 32];
                p += e.x * hv.x + e.y * hv.y + e.z * hv.z + e.w * hv.w;
            }
#pragma unroll
            for (int off = 16; off; off >>= 1) p += __shfl_xor_sync(0xffffffffu, p, off);
            if (lane == 0) wsh[w] = msk[it * 8 + w] ? p : -1e30f;
        }
        __syncthreads();

        float wv[8];
        float tm = -1e30f;
#pragma unroll
        for (int j = 0; j < 8; j++) { wv[j] = wsh[j]; tm = fmaxf(tm, wv[j]); }
        float mnew  = fmaxf(m, tm);
        float scale = __expf(m - mnew);
        l *= scale;
        acc.x *= scale; acc.y *= scale; acc.z *= scale; acc.w *= scale;
#pragma unroll
        for (int j = 0; j < 8; j++) {
            float pj = __expf(wv[j] - mnew);
            l += pj;
            float4 e = *(const float4*)(tb + j * 1024 + tid * 4);
            acc.x += pj * e.x; acc.y += pj * e.y; acc.z += pj * e.z; acc.w += pj * e.w;
        }
        m = mnew;
        __syncthreads();

        if (it + 2 < SEQ / 8) issue(it + 2);
        CP_COMMIT();
    }

    float inv = 1.f / l;
    float4 o = make_float4(acc.x * inv, acc.y * inv, acc.z * inv, acc.w * inv);
    *(float4*)(cat + (size_t)b * (2 * DIM) + DIM + tid * 4) = o;
}

// =====================================================================
// launcher
// =====================================================================
extern "C" void kernel_launch(void* const* d_in, const int* in_sizes, int n_in,
                              void* d_out, int out_size)
{
    (void)in_sizes; (void)n_in; (void)out_size;
    const int*   tokens   = (const int*)  d_in[0];
    const float* enc      = (const float*)d_in[1];
    const int*   encmask  = (const int*)  d_in[2];
    const float* dec_emb  = (const float*)d_in[3];
    const float* Wih0     = (const float*)d_in[4];
    const float* bih0     = (const float*)d_in[6];
    const float* bhh0     = (const float*)d_in[7];
    const float* Wih1     = (const float*)d_in[8];
    const float* bih1     = (const float*)d_in[10];
    const float* bhh1     = (const float*)d_in[11];
    const float* preout_w = (const float*)d_in[12];
    const float* preout_b = (const float*)d_in[13];
    const float* out_w    = (const float*)d_in[14];
    const float* out_b    = (const float*)d_in[15];
    float* logits = (float*)d_out;

    float *gi, *h0, *cat;
    uint32_t *apack, *w0p, *w1p, *prep;
    cudaGetSymbolAddress((void**)&gi,    g_gi);
    cudaGetSymbolAddress((void**)&h0,    g_h0);
    cudaGetSymbolAddress((void**)&cat,   g_cat);
    cudaGetSymbolAddress((void**)&apack, g_Apack);
    cudaGetSymbolAddress((void**)&w0p,   g_Wih0p);
    cudaGetSymbolAddress((void**)&w1p,   g_Wih1p);
    cudaGetSymbolAddress((void**)&prep,  g_Prep);

    static int smem_set = 0;
    if (!smem_set) {
        cudaFuncSetAttribute(logits256, cudaFuncAttributeMaxDynamicSharedMemorySize, LG256_SMEM_BYTES);
        cudaFuncSetAttribute(gemm_f16<0>, cudaFuncAttributeMaxDynamicSharedMemorySize, GM_SMEM_BYTES);
        cudaFuncSetAttribute(gemm_f16<1>, cudaFuncAttributeMaxDynamicSharedMemorySize, GM_SMEM_BYTES);
        cudaFuncSetAttribute(attn_kernel, cudaFuncAttributeMaxDynamicSharedMemorySize, ATTN_SMEM_BYTES);
        smem_set = 1;
    }

    // 0) weight prepacks for the small GEMMs only (cheap)
    prepack_w<<<(3 * DIM * 32) / 256, 256>>>(Wih0, 2 * DIM, 3 * DIM, DIM, w0p);
    prepack_w<<<(3 * DIM * 32) / 256, 256>>>(Wih1, DIM, 3 * DIM, DIM, w1p);
    prepack_w<<<(DIM * 64) / 256, 256>>>(preout_w, 2 * DIM, DIM, 2 * DIM, prep);

    // 1) gi0 = dec_emb[tokens] @ Wih0[:, :D]^T + bih0
    gemm_f16<0><<<2 * (3 * DIM / 128), 256, GM_SMEM_BYTES>>>(
        3 * DIM, DIM, dec_emb, DIM, tokens, w0p, bih0, gi, 3 * DIM);

    // 2) h0
    gru_gates<<<(BATCH * DIM) / 256, 256>>>(gi, bhh0, h0, DIM);

    // 3) gi1 = h0 @ Wih1^T + bih1
    gemm_f16<0><<<2 * (3 * DIM / 128), 256, GM_SMEM_BYTES>>>(
        3 * DIM, DIM, h0, DIM, nullptr, w1p, bih1, gi, 3 * DIM);

    // 4) fused: h1 gates + attention summary -> cat
    attn_kernel<<<BATCH, 256, ATTN_SMEM_BYTES>>>(enc, encmask, gi, bhh1, cat);

    // 5) preout: celu + direct fp16-pack into g_Apack
    gemm_f16<1><<<2 * (DIM / 128), 256, GM_SMEM_BYTES>>>(
        DIM, 2 * DIM, cat, 2 * DIM, nullptr, prep, preout_b, apack, 0);

    // 6) logits = Apack @ out_w^T + out_b   (256x128 tile, in-kernel B convert)
    logits256<<<VPAD / 128, 256, LG256_SMEM_BYTES>>>(apack, out_w, out_b, logits);
}

// round 13
// speedup vs baseline: 1.2961x; 1.1696x over previous
#include <cuda_runtime.h>
#include <cuda_fp16.h>
#include <cstdint>
#include <math.h>

#define BATCH 256
#define SEQ   512
#define DIM   1024
#define VOCAB 32003
#define VPAD  32128   // VOCAB padded to 128

// ---------------- scratch ----------------
__device__ float g_giP[2][BATCH * 3 * DIM];   // split-K partials (gi0 / gi1 reuse)
__device__ float g_h0[BATCH * DIM];
__device__ float g_cat[BATCH * 2 * DIM];
__device__ float g_preP[2][BATCH * DIM];      // preout split-K partials
__device__ uint32_t g_Apack[BATCH * (DIM / 2)];
__device__ uint32_t g_Wih0p[3 * DIM * (DIM / 2)];
__device__ uint32_t g_Wih1p[3 * DIM * (DIM / 2)];
__device__ uint32_t g_Prep [DIM * DIM];

__device__ __forceinline__ float celu1(float x) { return x > 0.f ? x : expm1f(x); }

// ---------------- fp16 helpers ----------------
__device__ __forceinline__ uint32_t h2pack(float x, float y) {
    __half2 h = __floats2half2_rn(x, y);
    return *(uint32_t*)&h;
}
__device__ __forceinline__ uint4 packq(float4 x, float4 y) {
    uint4 w;
    w.x = h2pack(x.x, x.y);
    w.y = h2pack(y.x, y.y);
    w.z = h2pack(x.z, x.w);
    w.w = h2pack(y.z, y.w);
    return w;
}
__device__ __forceinline__ void mmaf16(float* c, uint32_t a0, uint32_t a1, uint32_t a2,
                                       uint32_t a3, uint32_t b0, uint32_t b1) {
    asm volatile("mma.sync.aligned.m16n8k16.row.col.f32.f16.f16.f32 "
                 "{%0,%1,%2,%3}, {%4,%5,%6,%7}, {%8,%9}, {%0,%1,%2,%3};"
                 : "+f"(c[0]), "+f"(c[1]), "+f"(c[2]), "+f"(c[3])
                 : "r"(a0), "r"(a1), "r"(a2), "r"(a3), "r"(b0), "r"(b1));
}

// ---------------- cp.async helpers ----------------
#define CP_ASYNC16(dst, src) \
    asm volatile("cp.async.cg.shared.global [%0], [%1], 16;" :: "r"(dst), "l"(src))
#define CP_COMMIT() asm volatile("cp.async.commit_group;" ::: "memory")
#define CP_WAIT1()  asm volatile("cp.async.wait_group 1;" ::: "memory")
#define CP_WAIT2()  asm volatile("cp.async.wait_group 2;" ::: "memory")

#define LP    24
#define PLANE (128 * LP)
#define BUFW  (2 * PLANE)
#define NBUF  4
#define GM_SMEM_BYTES (NBUF * BUFW * 4)   // 98304 (small GEMMs)

// logits256 geometry
#define APLANE256 (256 * LP)
#define BUFW256   (APLANE256 + PLANE)
#define LG256_SMEM_BYTES (3 * BUFW256 * 4)  // 110592

// =====================================================================
// prepack_w: fp32 weights [Nsrc, ldw] -> swizzled fp16 rows [N, K/2 u32]
// =====================================================================
__global__ void __launch_bounds__(256)
prepack_w(const float* __restrict__ W, int ldw, int Nsrc, int K,
          uint32_t* __restrict__ out)
{
    int idx = blockIdx.x * 256 + threadIdx.x;
    int nch = K / 32;
    int row = idx / nch, ch = idx - row * nch;
    int srow = row < Nsrc ? row : Nsrc - 1;
    const float4* p = (const float4*)(W + (size_t)srow * ldw + ch * 32);
    float4 p0 = p[0], p1 = p[1], p2 = p[2], p3 = p[3];
    float4 p4 = p[4], p5 = p[5], p6 = p[6], p7 = p[7];
    int bp = (row >> 2) & 1;
    uint32_t* o = out + (size_t)row * (K / 2) + ch * 16;
    *(uint4*)(o + 4 * bp)           = packq(p0, p2);
    *(uint4*)(o + 4 * (bp ^ 1))     = packq(p1, p3);
    *(uint4*)(o + 8 + 4 * (bp ^ 1)) = packq(p4, p6);
    *(uint4*)(o + 8 + 4 * bp)       = packq(p5, p7);
}

// =====================================================================
// gemm_f16 (small GEMMs, split-K): partial C_z = A[:, zK:] @ B[:, zK:]^T
// bias applied only for z==0. grid = (2*N/128, 1, ZSPLIT).
// Ksub = K per z-slice; bpitch = full K/2 words (packed row pitch).
// =====================================================================
__global__ void __launch_bounds__(256)
gemm_f16(int N, int Ksub, int bpitch,
         const float* __restrict__ A, int lda, const int* __restrict__ gather,
         const uint32_t* __restrict__ Bpack,
         const float* __restrict__ bias,
         float* __restrict__ Cout, int ldc, size_t czstride)
{
    extern __shared__ uint32_t sm[];
    const uint32_t smb = (uint32_t)__cvta_generic_to_shared(sm);
    const int t    = threadIdx.x;
    const int lane = t & 31;
    const int wid  = t >> 5;
    const int wm   = wid >> 2;
    const int wn   = wid & 3;
    const int bm   = blockIdx.x & 1;
    const int bn   = blockIdx.x >> 1;
    const int kz   = blockIdx.z;
    const int NCH  = Ksub / 32;

    const int rb   = t >> 1;
    const int half = t & 1;
    const int bp   = (rb >> 2) & 1;
    const int wq0  = 8 * half + 4 * (bp ^ half);
    const int wq1  = 8 * half + 4 * ((bp ^ 1) ^ half);

    int arow = bm * 128 + rb;
    if (gather) arow = gather[arow];
    const float* asrc = A + (size_t)arow * lda + kz * Ksub + half * 16;
    const uint32_t* bsrc = Bpack + (size_t)(bn * 128 + rb) * bpitch
                         + kz * (Ksub / 2) + half * 8;
    const uint32_t dstOff = (uint32_t)(rb * LP + half * 8) * 4;
    float* C = Cout + (size_t)kz * czstride;

    float4 pa[4];
    auto ldA = [&](int ch) {
        const float4* qa = (const float4*)(asrc + ch * 32);
        pa[0] = qa[0]; pa[1] = qa[1]; pa[2] = qa[2]; pa[3] = qa[3];
    };
    auto stA = [&](int buf) {
        uint32_t* ba = sm + buf * BUFW + rb * LP;
        *(uint4*)(ba + wq0) = packq(pa[0], pa[2]);
        *(uint4*)(ba + wq1) = packq(pa[1], pa[3]);
    };
    auto issueB = [&](int ch) {
        int buf = ch & (NBUF - 1);
        uint32_t d = smb + (uint32_t)buf * BUFW * 4 + (uint32_t)PLANE * 4 + dstOff;
        const uint32_t* s = bsrc + ch * 16;
        CP_ASYNC16(d, s);
        CP_ASYNC16(d + 16, s + 4);
    };

    float acc[4][4][4];
#pragma unroll
    for (int i = 0; i < 4; i++)
#pragma unroll
        for (int j = 0; j < 4; j++)
#pragma unroll
            for (int k = 0; k < 4; k++) acc[i][j][k] = 0.f;

    const int c_ = lane & 3;
    const int bt = (lane >> 4) & 1;
    const int q2 = (c_ >> 1) ^ bt;
    const int rA = wm * 64 + (lane >> 2);
    const int cB = wn * 32 + (lane >> 2);

    ldA(0);
    issueB(0); CP_COMMIT();
    issueB(1); CP_COMMIT();
    issueB(2); CP_COMMIT();
    stA(0);
    ldA(1);
    CP_WAIT2();
    __syncthreads();

    for (int ch = 0; ch < NCH; ch++) {
        if (ch + 1 < NCH) stA((ch + 1) & (NBUF - 1));
        if (ch + 2 < NCH) ldA(ch + 2);
        if (ch + 3 < NCH) { issueB(ch + 3); CP_COMMIT(); }
        CP_WAIT2();

        const uint32_t* Ab = sm + (ch & (NBUF - 1)) * BUFW;
        const uint32_t* Bb = Ab + PLANE;
#pragma unroll
        for (int h = 0; h < 2; h++) {
            const int off = 8 * h + 4 * (q2 ^ h) + 2 * (c_ & 1);
            uint2 af[4][2];
#pragma unroll
            for (int mt = 0; mt < 4; mt++) {
                af[mt][0] = *(const uint2*)(Ab + (rA + 16 * mt) * LP + off);
                af[mt][1] = *(const uint2*)(Ab + (rA + 16 * mt + 8) * LP + off);
            }
#pragma unroll
            for (int nt = 0; nt < 4; nt++) {
                uint2 bf = *(const uint2*)(Bb + (cB + 8 * nt) * LP + off);
#pragma unroll
                for (int mt = 0; mt < 4; mt++)
                    mmaf16(acc[mt][nt], af[mt][0].x, af[mt][1].x,
                           af[mt][0].y, af[mt][1].y, bf.x, bf.y);
            }
        }
        __syncthreads();
    }

    const int n0 = bn * 128 + wn * 32 + 2 * c_;
    float bz[8];
#pragma unroll
    for (int nt = 0; nt < 4; nt++) {
        bz[2 * nt]     = (kz == 0) ? bias[n0 + 8 * nt]     : 0.f;
        bz[2 * nt + 1] = (kz == 0) ? bias[n0 + 8 * nt + 1] : 0.f;
    }
    const int m0 = bm * 128 + wm * 64 + (lane >> 2);
#pragma unroll
    for (int mt = 0; mt < 4; mt++) {
        float* r0 = C + (size_t)(m0 + 16 * mt) * ldc;
        float* r1 = r0 + (size_t)8 * ldc;
#pragma unroll
        for (int nt = 0; nt < 4; nt++) {
            int n = n0 + 8 * nt;
            r0[n]     = acc[mt][nt][0] + bz[2 * nt];
            r0[n + 1] = acc[mt][nt][1] + bz[2 * nt + 1];
            r1[n]     = acc[mt][nt][2] + bz[2 * nt];
            r1[n + 1] = acc[mt][nt][3] + bz[2 * nt + 1];
        }
    }
}

// =====================================================================
// prepack_combine: celu(P0 + P1) -> swizzled fp16 g_Apack (proven formula)
// =====================================================================
__global__ void __launch_bounds__(256)
prepack_combine(const float* __restrict__ P0, const float* __restrict__ P1,
                uint32_t* __restrict__ out)
{
    int idx = blockIdx.x * 256 + threadIdx.x;   // 8192 = 256 rows x 32 chunks
    int row = idx >> 5, ch = idx & 31;
    const float4* a0 = (const float4*)(P0 + (size_t)row * DIM + ch * 32);
    const float4* a1 = (const float4*)(P1 + (size_t)row * DIM + ch * 32);
    float4 q[8];
#pragma unroll
    for (int i = 0; i < 8; i++) {
        float4 x = a0[i], y = a1[i];
        q[i].x = celu1(x.x + y.x);
        q[i].y = celu1(x.y + y.y);
        q[i].z = celu1(x.z + y.z);
        q[i].w = celu1(x.w + y.w);
    }
    int bp = (row >> 2) & 1;
    uint32_t* o = out + (size_t)row * (DIM / 2) + ch * 16;
    *(uint4*)(o + 4 * bp)           = packq(q[0], q[2]);
    *(uint4*)(o + 4 * (bp ^ 1))     = packq(q[1], q[3]);
    *(uint4*)(o + 8 + 4 * (bp ^ 1)) = packq(q[4], q[6]);
    *(uint4*)(o + 8 + 4 * bp)       = packq(q[5], q[7]);
}

// =====================================================================
// logits256 (unchanged from R12): 256x128 tile, in-kernel B convert.
// =====================================================================
__global__ void __launch_bounds__(256, 1)
logits256(const uint32_t* __restrict__ Apack, const float* __restrict__ Bw,
          const float* __restrict__ bias, float* __restrict__ C)
{
    extern __shared__ uint32_t sm[];
    const uint32_t smb = (uint32_t)__cvta_generic_to_shared(sm);
    const int t    = threadIdx.x;
    const int lane = t & 31;
    const int wid  = t >> 5;
    const int wm   = wid & 3;
    const int wn   = wid >> 2;
    const int bn   = blockIdx.x;

    const int rb   = t >> 1;
    const int half = t & 1;
    const int bpB  = (rb >> 2) & 1;
    const int wq0  = 8 * half + 4 * (bpB ^ half);
    const int wq1  = 8 * half + 4 * ((bpB ^ 1) ^ half);

    int ng = bn * 128 + rb;
    if (ng > VOCAB - 1) ng = VOCAB - 1;
    const float* bsrc = Bw + (size_t)ng * DIM + half * 16;
    const uint32_t* srcA0 = Apack + (size_t)rb * (DIM / 2) + half * 8;
    const uint32_t* srcA1 = Apack + (size_t)(rb + 128) * (DIM / 2) + half * 8;
    const uint32_t dstA0 = (uint32_t)(rb * LP + half * 8) * 4;
    const uint32_t dstA1 = (uint32_t)((rb + 128) * LP + half * 8) * 4;

    float4 pf[4];
    auto ldB = [&](int ch) {
        const float4* p = (const float4*)(bsrc + ch * 32);
        pf[0] = p[0]; pf[1] = p[1]; pf[2] = p[2]; pf[3] = p[3];
    };
    auto stB = [&](int buf) {
        uint32_t* base = sm + buf * BUFW256 + APLANE256 + rb * LP;
        *(uint4*)(base + wq0) = packq(pf[0], pf[2]);
        *(uint4*)(base + wq1) = packq(pf[1], pf[3]);
    };
    auto issueA = [&](int ch, int buf) {
        uint32_t d = smb + (uint32_t)buf * BUFW256 * 4;
        const uint32_t* s0 = srcA0 + ch * 16;
        const uint32_t* s1 = srcA1 + ch * 16;
        CP_ASYNC16(d + dstA0, s0);
        CP_ASYNC16(d + dstA0 + 16, s0 + 4);
        CP_ASYNC16(d + dstA1, s1);
        CP_ASYNC16(d + dstA1 + 16, s1 + 4);
        CP_COMMIT();
    };

    float acc[4][8][4];
#pragma unroll
    for (int i = 0; i < 4; i++)
#pragma unroll
        for (int j = 0; j < 8; j++)
#pragma unroll
            for (int k = 0; k < 4; k++) acc[i][j][k] = 0.f;

    const int c_ = lane & 3;
    const int bt = (lane >> 4) & 1;
    const int q2 = (c_ >> 1) ^ bt;
    const int rA = wm * 64 + (lane >> 2);
    const int cB = wn * 64 + (lane >> 2);

    ldB(0);
    issueA(0, 0);
    issueA(1, 1);
    stB(0);
    ldB(1);
    CP_WAIT1();
    __syncthreads();

    const int NCH = DIM / 32;
    int bufC = 0;
    for (int ch = 0; ch < NCH; ch++) {
        const int bufN  = bufC + 1 == 3 ? 0 : bufC + 1;
        const int bufNN = bufN + 1 == 3 ? 0 : bufN + 1;
        if (ch + 1 < NCH) stB(bufN);
        if (ch + 2 < NCH) ldB(ch + 2);
        if (ch + 2 < NCH) issueA(ch + 2, bufNN);

        const uint32_t* Ab = sm + bufC * BUFW256;
        const uint32_t* Bb = Ab + APLANE256;
#pragma unroll
        for (int h = 0; h < 2; h++) {
            const int off = 8 * h + 4 * (q2 ^ h) + 2 * (c_ & 1);
            uint2 af[4][2];
#pragma unroll
            for (int mt = 0; mt < 4; mt++) {
                af[mt][0] = *(const uint2*)(Ab + (rA + 16 * mt) * LP + off);
                af[mt][1] = *(const uint2*)(Ab + (rA + 16 * mt + 8) * LP + off);
            }
#pragma unroll
            for (int nt = 0; nt < 8; nt++) {
                uint2 bf = *(const uint2*)(Bb + (cB + 8 * nt) * LP + off);
#pragma unroll
                for (int mt = 0; mt < 4; mt++)
                    mmaf16(acc[mt][nt], af[mt][0].x, af[mt][1].x,
                           af[mt][0].y, af[mt][1].y, bf.x, bf.y);
            }
        }
        CP_WAIT1();
        __syncthreads();
        bufC = bufN;
    }

    const int n0 = bn * 128 + wn * 64 + 2 * c_;
    float bz[16];
#pragma unroll
    for (int nt = 0; nt < 8; nt++) {
        int n = n0 + 8 * nt;
        bz[2 * nt]     = (n     < VOCAB) ? bias[n]     : 0.f;
        bz[2 * nt + 1] = (n + 1 < VOCAB) ? bias[n + 1] : 0.f;
    }
    const int m0 = wm * 64 + (lane >> 2);
#pragma unroll
    for (int mt = 0; mt < 4; mt++) {
        float* r0 = C + (size_t)(m0 + 16 * mt) * VOCAB;
        float* r1 = r0 + (size_t)8 * VOCAB;
#pragma unroll
        for (int nt = 0; nt < 8; nt++) {
            int n = n0 + 8 * nt;
            if (n < VOCAB) {
                r0[n] = acc[mt][nt][0] + bz[2 * nt];
                r1[n] = acc[mt][nt][2] + bz[2 * nt];
            }
            if (n + 1 < VOCAB) {
                r0[n + 1] = acc[mt][nt][1] + bz[2 * nt + 1];
                r1[n + 1] = acc[mt][nt][3] + bz[2 * nt + 1];
            }
        }
    }
}

// =====================================================================
// GRU gates from split-K partials: g = P0 + P1 (bias already in P0's z=0)
// =====================================================================
__global__ void gru_gates(const float* __restrict__ P0, const float* __restrict__ P1,
                          const float* __restrict__ bhh,
                          float* __restrict__ h, int ldh)
{
    int idx = blockIdx.x * blockDim.x + threadIdx.x;
    int b = idx >> 10, d = idx & 1023;
    const float* g0 = P0 + (size_t)b * (3 * DIM);
    const float* g1 = P1 + (size_t)b * (3 * DIM);
    float gr = g0[d]           + g1[d];
    float gz = g0[DIM + d]     + g1[DIM + d];
    float gn = g0[2 * DIM + d] + g1[2 * DIM + d];
    float r = 1.f / (1.f + expf(-(gr + bhh[d])));
    float z = 1.f / (1.f + expf(-(gz + bhh[DIM + d])));
    float n = tanhf(gn + r * bhh[2 * DIM + d]);
    h[(size_t)b * ldh + d] = (1.f - z) * n;
}

// =====================================================================
// Fused attention: h1 gates from split-K partials + online softmax.
// =====================================================================
#define ATTN_SMEM_BYTES ((1024 + 2 * 8 * 1024 + 8 + 512) * 4)

__global__ void __launch_bounds__(256)
attn_kernel(const float* __restrict__ enc, const int* __restrict__ mask,
            const float* __restrict__ P0, const float* __restrict__ P1,
            const float* __restrict__ bhh, float* __restrict__ cat)
{
    extern __shared__ float smf[];
    float* h1s   = smf;
    float* tiles = smf + 1024;
    float* wsh   = smf + 1024 + 16384;
    int*   msk   = (int*)(smf + 1024 + 16384 + 8);

    const int b   = blockIdx.x;
    const int tid = threadIdx.x;
    const float* encb  = enc  + (size_t)b * SEQ * DIM;
    const int*   maskb = mask + b * SEQ;

    msk[tid]       = maskb[tid];
    msk[tid + 256] = maskb[tid + 256];

    {
        const float* g0 = P0 + (size_t)b * (3 * DIM);
        const float* g1 = P1 + (size_t)b * (3 * DIM);
        int d = tid * 4;
        float4 vr0 = *(const float4*)(g0 + d);
        float4 vz0 = *(const float4*)(g0 + DIM + d);
        float4 vn0 = *(const float4*)(g0 + 2 * DIM + d);
        float4 vr1 = *(const float4*)(g1 + d);
        float4 vz1 = *(const float4*)(g1 + DIM + d);
        float4 vn1 = *(const float4*)(g1 + 2 * DIM + d);
        float4 br = *(const float4*)(bhh + d);
        float4 bz = *(const float4*)(bhh + DIM + d);
        float4 bn = *(const float4*)(bhh + 2 * DIM + d);
        float h[4];
        {
            float r0 = 1.f / (1.f + expf(-(vr0.x + vr1.x + br.x)));
            float z0 = 1.f / (1.f + expf(-(vz0.x + vz1.x + bz.x)));
            h[0] = (1.f - z0) * tanhf(vn0.x + vn1.x + r0 * bn.x);
            float r1 = 1.f / (1.f + expf(-(vr0.y + vr1.y + br.y)));
            float z1 = 1.f / (1.f + expf(-(vz0.y + vz1.y + bz.y)));
            h[1] = (1.f - z1) * tanhf(vn0.y + vn1.y + r1 * bn.y);
            float r2 = 1.f / (1.f + expf(-(vr0.z + vr1.z + br.z)));
            float z2 = 1.f / (1.f + expf(-(vz0.z + vz1.z + bz.z)));
            h[2] = (1.f - z2) * tanhf(vn0.z + vn1.z + r2 * bn.z);
            float r3 = 1.f / (1.f + expf(-(vr0.w + vr1.w + br.w)));
            float z3 = 1.f / (1.f + expf(-(vz0.w + vz1.w + bz.w)));
            h[3] = (1.f - z3) * tanhf(vn0.w + vn1.w + r3 * bn.w);
        }
        float4 hv = make_float4(h[0], h[1], h[2], h[3]);
        *(float4*)(h1s + d) = hv;
        *(float4*)(cat + (size_t)b * (2 * DIM) + d) = hv;
    }

    const uint32_t tbase = (uint32_t)__cvta_generic_to_shared(tiles);
    auto issue = [&](int it) {
        const float* src = encb + (size_t)it * 8 * DIM + tid * 4;
        uint32_t dst = tbase + (uint32_t)((it & 1) * 32768 + tid * 16);
#pragma unroll
        for (int i = 0; i < 8; i++)
            CP_ASYNC16(dst + i * 4096, (const void*)(src + i * 1024));
    };

    issue(0); CP_COMMIT();
    issue(1); CP_COMMIT();

    float m = -1e30f, l = 0.f;
    float4 acc = make_float4(0.f, 0.f, 0.f, 0.f);

    for (int it = 0; it < SEQ / 8; it++) {
        CP_WAIT1();
        __syncthreads();
        const float* tb = tiles + (it & 1) * 8192;

        {
            int w = tid >> 5, lane = tid & 31;
            float p = 0.f;
            const float4* er = (const float4*)(tb + w * 1024);
            const float4* hr = (const float4*)h1s;
#pragma unroll
            for (int i = 0; i < 8; i++) {
                float4 e  = er[lane + i * 32];
                float4 hv = hr[lane + i * 32];
                p += e.x * hv.x + e.y * hv.y + e.z * hv.z + e.w * hv.w;
            }
#pragma unroll
            for (int off = 16; off; off >>= 1) p += __shfl_xor_sync(0xffffffffu, p, off);
            if (lane == 0) wsh[w] = msk[it * 8 + w] ? p : -1e30f;
        }
        __syncthreads();

        float wv[8];
        float tm = -1e30f;
#pragma unroll
        for (int j = 0; j < 8; j++) { wv[j] = wsh[j]; tm = fmaxf(tm, wv[j]); }
        float mnew  = fmaxf(m, tm);
        float scale = __expf(m - mnew);
        l *= scale;
        acc.x *= scale; acc.y *= scale; acc.z *= scale; acc.w *= scale;
#pragma unroll
        for (int j = 0; j < 8; j++) {
            float pj = __expf(wv[j] - mnew);
            l += pj;
            float4 e = *(const float4*)(tb + j * 1024 + tid * 4);
            acc.x += pj * e.x; acc.y += pj * e.y; acc.z += pj * e.z; acc.w += pj * e.w;
        }
        m = mnew;
        __syncthreads();

        if (it + 2 < SEQ / 8) issue(it + 2);
        CP_COMMIT();
    }

    float inv = 1.f / l;
    float4 o = make_float4(acc.x * inv, acc.y * inv, acc.z * inv, acc.w * inv);
    *(float4*)(cat + (size_t)b * (2 * DIM) + DIM + tid * 4) = o;
}

// =====================================================================
// launcher
// =====================================================================
extern "C" void kernel_launch(void* const* d_in, const int* in_sizes, int n_in,
                              void* d_out, int out_size)
{
    (void)in_sizes; (void)n_in; (void)out_size;
    const int*   tokens   = (const int*)  d_in[0];
    const float* enc      = (const float*)d_in[1];
    const int*   encmask  = (const int*)  d_in[2];
    const float* dec_emb  = (const float*)d_in[3];
    const float* Wih0     = (const float*)d_in[4];
    const float* bih0     = (const float*)d_in[6];
    const float* bhh0     = (const float*)d_in[7];
    const float* Wih1     = (const float*)d_in[8];
    const float* bih1     = (const float*)d_in[10];
    const float* bhh1     = (const float*)d_in[11];
    const float* preout_w = (const float*)d_in[12];
    const float* preout_b = (const float*)d_in[13];
    const float* out_w    = (const float*)d_in[14];
    const float* out_b    = (const float*)d_in[15];
    float* logits = (float*)d_out;

    float *giP, *h0, *cat, *preP;
    uint32_t *apack, *w0p, *w1p, *prep;
    cudaGetSymbolAddress((void**)&giP,   g_giP);
    cudaGetSymbolAddress((void**)&h0,    g_h0);
    cudaGetSymbolAddress((void**)&cat,   g_cat);
    cudaGetSymbolAddress((void**)&preP,  g_preP);
    cudaGetSymbolAddress((void**)&apack, g_Apack);
    cudaGetSymbolAddress((void**)&w0p,   g_Wih0p);
    cudaGetSymbolAddress((void**)&w1p,   g_Wih1p);
    cudaGetSymbolAddress((void**)&prep,  g_Prep);

    const size_t GI_STRIDE  = (size_t)BATCH * 3 * DIM;
    const size_t PRE_STRIDE = (size_t)BATCH * DIM;

    static int smem_set = 0;
    if (!smem_set) {
        cudaFuncSetAttribute(logits256, cudaFuncAttributeMaxDynamicSharedMemorySize, LG256_SMEM_BYTES);
        cudaFuncSetAttribute(gemm_f16, cudaFuncAttributeMaxDynamicSharedMemorySize, GM_SMEM_BYTES);
        cudaFuncSetAttribute(attn_kernel, cudaFuncAttributeMaxDynamicSharedMemorySize, ATTN_SMEM_BYTES);
        smem_set = 1;
    }

    // 0) weight prepacks for the small GEMMs
    prepack_w<<<(3 * DIM * 32) / 256, 256>>>(Wih0, 2 * DIM, 3 * DIM, DIM, w0p);
    prepack_w<<<(3 * DIM * 32) / 256, 256>>>(Wih1, DIM, 3 * DIM, DIM, w1p);
    prepack_w<<<(DIM * 64) / 256, 256>>>(preout_w, 2 * DIM, DIM, 2 * DIM, prep);

    // 1) gi0 split-K partials (z=0 carries bias)
    gemm_f16<<<dim3(2 * (3 * DIM / 128), 1, 2), 256, GM_SMEM_BYTES>>>(
        3 * DIM, DIM / 2, DIM / 2, dec_emb, DIM, tokens, w0p, bih0,
        giP, 3 * DIM, GI_STRIDE);

    // 2) h0 = gates(P0 + P1)
    gru_gates<<<(BATCH * DIM) / 256, 256>>>(giP, giP + GI_STRIDE, bhh0, h0, DIM);

    // 3) gi1 split-K partials
    gemm_f16<<<dim3(2 * (3 * DIM / 128), 1, 2), 256, GM_SMEM_BYTES>>>(
        3 * DIM, DIM / 2, DIM / 2, h0, DIM, nullptr, w1p, bih1,
        giP, 3 * DIM, GI_STRIDE);

    // 4) fused: h1 gates (P0+P1) + attention summary -> cat
    attn_kernel<<<BATCH, 256, ATTN_SMEM_BYTES>>>(enc, encmask, giP, giP + GI_STRIDE, bhh1, cat);

    // 5) preout split-K partials (z=0 carries bias)
    gemm_f16<<<dim3(2 * (DIM / 128), 1, 2), 256, GM_SMEM_BYTES>>>(
        DIM, DIM, DIM, cat, 2 * DIM, nullptr, prep, preout_b,
        preP, DIM, PRE_STRIDE);

    // 6) celu(P0+P1) + fp16 pack -> g_Apack
    prepack_combine<<<32, 256>>>(preP, preP + PRE_STRIDE, apack);

    // 7) logits = Apack @ out_w^T + out_b
    logits256<<<VPAD / 128, 256, LG256_SMEM_BYTES>>>(apack, out_w, out_b, logits);
}

// round 14
// speedup vs baseline: 1.3656x; 1.0536x over previous
#include <cuda_runtime.h>
#include <cuda_fp16.h>
#include <cstdint>
#include <math.h>

#define BATCH 256
#define SEQ   512
#define DIM   1024
#define VOCAB 32003
#define VPAD  32128   // VOCAB padded to 128

// ---------------- scratch ----------------
__device__ float g_giP[4][BATCH * 3 * DIM];   // split-K partials (gi0 / gi1 reuse)
__device__ float g_h0[BATCH * DIM];
__device__ float g_cat[BATCH * 2 * DIM];
__device__ float g_preP[4][BATCH * DIM];      // preout split-K partials
__device__ uint32_t g_Apack[BATCH * (DIM / 2)];
__device__ uint32_t g_Wih0p[3 * DIM * (DIM / 2)];
__device__ uint32_t g_Wih1p[3 * DIM * (DIM / 2)];
__device__ uint32_t g_Prep [DIM * DIM];

__device__ __forceinline__ float celu1(float x) { return x > 0.f ? x : expm1f(x); }

// ---------------- fp16 helpers ----------------
__device__ __forceinline__ uint32_t h2pack(float x, float y) {
    __half2 h = __floats2half2_rn(x, y);
    return *(uint32_t*)&h;
}
__device__ __forceinline__ uint4 packq(float4 x, float4 y) {
    uint4 w;
    w.x = h2pack(x.x, x.y);
    w.y = h2pack(y.x, y.y);
    w.z = h2pack(x.z, x.w);
    w.w = h2pack(y.z, y.w);
    return w;
}
__device__ __forceinline__ void mmaf16(float* c, uint32_t a0, uint32_t a1, uint32_t a2,
                                       uint32_t a3, uint32_t b0, uint32_t b1) {
    asm volatile("mma.sync.aligned.m16n8k16.row.col.f32.f16.f16.f32 "
                 "{%0,%1,%2,%3}, {%4,%5,%6,%7}, {%8,%9}, {%0,%1,%2,%3};"
                 : "+f"(c[0]), "+f"(c[1]), "+f"(c[2]), "+f"(c[3])
                 : "r"(a0), "r"(a1), "r"(a2), "r"(a3), "r"(b0), "r"(b1));
}

// ---------------- cp.async helpers ----------------
#define CP_ASYNC16(dst, src) \
    asm volatile("cp.async.cg.shared.global [%0], [%1], 16;" :: "r"(dst), "l"(src))
#define CP_COMMIT() asm volatile("cp.async.commit_group;" ::: "memory")
#define CP_WAIT1()  asm volatile("cp.async.wait_group 1;" ::: "memory")
#define CP_WAIT2()  asm volatile("cp.async.wait_group 2;" ::: "memory")

#define LP    24
#define PLANE (128 * LP)
#define BUFW  (2 * PLANE)
#define NBUF  4
#define GM_SMEM_BYTES (NBUF * BUFW * 4)   // 98304 (small GEMMs)

// logits256 geometry
#define APLANE256 (256 * LP)
#define BUFW256   (APLANE256 + PLANE)
#define LG256_SMEM_BYTES (3 * BUFW256 * 4)  // 110592

// =====================================================================
// prepack_all: fused weight prepack for Wih0, Wih1, preout_w.
// blocks [0,384): Wih0 (3072 rows, K=1024, ldw=2048)
// blocks [384,768): Wih1 (3072 rows, K=1024, ldw=1024)
// blocks [768,1024): preout_w (1024 rows, K=2048, ldw=2048)
// =====================================================================
__global__ void __launch_bounds__(256)
prepack_all(const float* __restrict__ Wih0, const float* __restrict__ Wih1,
            const float* __restrict__ Pw,
            uint32_t* __restrict__ w0p, uint32_t* __restrict__ w1p,
            uint32_t* __restrict__ prep)
{
    const float* W;
    uint32_t* out;
    int ldw, K, idx;
    int blk = blockIdx.x;
    if (blk < 384)      { W = Wih0; out = w0p;  ldw = 2 * DIM; K = DIM;     idx = blk * 256 + threadIdx.x; }
    else if (blk < 768) { W = Wih1; out = w1p;  ldw = DIM;     K = DIM;     idx = (blk - 384) * 256 + threadIdx.x; }
    else                { W = Pw;   out = prep; ldw = 2 * DIM; K = 2 * DIM; idx = (blk - 768) * 256 + threadIdx.x; }
    int nch = K / 32;
    int row = idx / nch, ch = idx - row * nch;
    const float4* p = (const float4*)(W + (size_t)row * ldw + ch * 32);
    float4 p0 = p[0], p1 = p[1], p2 = p[2], p3 = p[3];
    float4 p4 = p[4], p5 = p[5], p6 = p[6], p7 = p[7];
    int bp = (row >> 2) & 1;
    uint32_t* o = out + (size_t)row * (K / 2) + ch * 16;
    *(uint4*)(o + 4 * bp)           = packq(p0, p2);
    *(uint4*)(o + 4 * (bp ^ 1))     = packq(p1, p3);
    *(uint4*)(o + 8 + 4 * (bp ^ 1)) = packq(p4, p6);
    *(uint4*)(o + 8 + 4 * bp)       = packq(p5, p7);
}

// =====================================================================
// gemm_f16 (small GEMMs, split-K): partial C_z = A[:, z*Ksub:] @ B[:, z*Ksub:]^T
// bias applied only for z==0. grid = (2*N/128, 1, ZSPLIT).
// =====================================================================
__global__ void __launch_bounds__(256)
gemm_f16(int N, int Ksub, int bpitch,
         const float* __restrict__ A, int lda, const int* __restrict__ gather,
         const uint32_t* __restrict__ Bpack,
         const float* __restrict__ bias,
         float* __restrict__ Cout, int ldc, size_t czstride)
{
    extern __shared__ uint32_t sm[];
    const uint32_t smb = (uint32_t)__cvta_generic_to_shared(sm);
    const int t    = threadIdx.x;
    const int lane = t & 31;
    const int wid  = t >> 5;
    const int wm   = wid >> 2;
    const int wn   = wid & 3;
    const int bm   = blockIdx.x & 1;
    const int bn   = blockIdx.x >> 1;
    const int kz   = blockIdx.z;
    const int NCH  = Ksub / 32;

    const int rb   = t >> 1;
    const int half = t & 1;
    const int bp   = (rb >> 2) & 1;
    const int wq0  = 8 * half + 4 * (bp ^ half);
    const int wq1  = 8 * half + 4 * ((bp ^ 1) ^ half);

    int arow = bm * 128 + rb;
    if (gather) arow = gather[arow];
    const float* asrc = A + (size_t)arow * lda + kz * Ksub + half * 16;
    const uint32_t* bsrc = Bpack + (size_t)(bn * 128 + rb) * bpitch
                         + kz * (Ksub / 2) + half * 8;
    const uint32_t dstOff = (uint32_t)(rb * LP + half * 8) * 4;
    float* C = Cout + (size_t)kz * czstride;

    float4 pa[4];
    auto ldA = [&](int ch) {
        const float4* qa = (const float4*)(asrc + ch * 32);
        pa[0] = qa[0]; pa[1] = qa[1]; pa[2] = qa[2]; pa[3] = qa[3];
    };
    auto stA = [&](int buf) {
        uint32_t* ba = sm + buf * BUFW + rb * LP;
        *(uint4*)(ba + wq0) = packq(pa[0], pa[2]);
        *(uint4*)(ba + wq1) = packq(pa[1], pa[3]);
    };
    auto issueB = [&](int ch) {
        int buf = ch & (NBUF - 1);
        uint32_t d = smb + (uint32_t)buf * BUFW * 4 + (uint32_t)PLANE * 4 + dstOff;
        const uint32_t* s = bsrc + ch * 16;
        CP_ASYNC16(d, s);
        CP_ASYNC16(d + 16, s + 4);
    };

    float acc[4][4][4];
#pragma unroll
    for (int i = 0; i < 4; i++)
#pragma unroll
        for (int j = 0; j < 4; j++)
#pragma unroll
            for (int k = 0; k < 4; k++) acc[i][j][k] = 0.f;

    const int c_ = lane & 3;
    const int bt = (lane >> 4) & 1;
    const int q2 = (c_ >> 1) ^ bt;
    const int rA = wm * 64 + (lane >> 2);
    const int cB = wn * 32 + (lane >> 2);

    ldA(0);
    issueB(0); CP_COMMIT();
    issueB(1); CP_COMMIT();
    issueB(2); CP_COMMIT();
    stA(0);
    ldA(1);
    CP_WAIT2();
    __syncthreads();

    for (int ch = 0; ch < NCH; ch++) {
        if (ch + 1 < NCH) stA((ch + 1) & (NBUF - 1));
        if (ch + 2 < NCH) ldA(ch + 2);
        if (ch + 3 < NCH) { issueB(ch + 3); CP_COMMIT(); }
        CP_WAIT2();

        const uint32_t* Ab = sm + (ch & (NBUF - 1)) * BUFW;
        const uint32_t* Bb = Ab + PLANE;
#pragma unroll
        for (int h = 0; h < 2; h++) {
            const int off = 8 * h + 4 * (q2 ^ h) + 2 * (c_ & 1);
            uint2 af[4][2];
#pragma unroll
            for (int mt = 0; mt < 4; mt++) {
                af[mt][0] = *(const uint2*)(Ab + (rA + 16 * mt) * LP + off);
                af[mt][1] = *(const uint2*)(Ab + (rA + 16 * mt + 8) * LP + off);
            }
#pragma unroll
            for (int nt = 0; nt < 4; nt++) {
                uint2 bf = *(const uint2*)(Bb + (cB + 8 * nt) * LP + off);
#pragma unroll
                for (int mt = 0; mt < 4; mt++)
                    mmaf16(acc[mt][nt], af[mt][0].x, af[mt][1].x,
                           af[mt][0].y, af[mt][1].y, bf.x, bf.y);
            }
        }
        __syncthreads();
    }

    const int n0 = bn * 128 + wn * 32 + 2 * c_;
    float bz[8];
#pragma unroll
    for (int nt = 0; nt < 4; nt++) {
        bz[2 * nt]     = (kz == 0) ? bias[n0 + 8 * nt]     : 0.f;
        bz[2 * nt + 1] = (kz == 0) ? bias[n0 + 8 * nt + 1] : 0.f;
    }
    const int m0 = bm * 128 + wm * 64 + (lane >> 2);
#pragma unroll
    for (int mt = 0; mt < 4; mt++) {
        float* r0 = C + (size_t)(m0 + 16 * mt) * ldc;
        float* r1 = r0 + (size_t)8 * ldc;
#pragma unroll
        for (int nt = 0; nt < 4; nt++) {
            int n = n0 + 8 * nt;
            r0[n]     = acc[mt][nt][0] + bz[2 * nt];
            r0[n + 1] = acc[mt][nt][1] + bz[2 * nt + 1];
            r1[n]     = acc[mt][nt][2] + bz[2 * nt];
            r1[n + 1] = acc[mt][nt][3] + bz[2 * nt + 1];
        }
    }
}

// =====================================================================
// prepack_combine: celu(P0+P1+P2+P3) -> swizzled fp16 g_Apack
// =====================================================================
__global__ void __launch_bounds__(256)
prepack_combine(const float* __restrict__ P, size_t stride,
                uint32_t* __restrict__ out)
{
    int idx = blockIdx.x * 256 + threadIdx.x;   // 8192 = 256 rows x 32 chunks
    int row = idx >> 5, ch = idx & 31;
    size_t base = (size_t)row * DIM + ch * 32;
    float4 q[8];
#pragma unroll
    for (int i = 0; i < 8; i++) {
        float4 s = *(const float4*)(P + base + i * 4);
#pragma unroll
        for (int z = 1; z < 4; z++) {
            float4 y = *(const float4*)(P + z * stride + base + i * 4);
            s.x += y.x; s.y += y.y; s.z += y.z; s.w += y.w;
        }
        q[i].x = celu1(s.x);
        q[i].y = celu1(s.y);
        q[i].z = celu1(s.z);
        q[i].w = celu1(s.w);
    }
    int bp = (row >> 2) & 1;
    uint32_t* o = out + (size_t)row * (DIM / 2) + ch * 16;
    *(uint4*)(o + 4 * bp)           = packq(q[0], q[2]);
    *(uint4*)(o + 4 * (bp ^ 1))     = packq(q[1], q[3]);
    *(uint4*)(o + 8 + 4 * (bp ^ 1)) = packq(q[4], q[6]);
    *(uint4*)(o + 8 + 4 * bp)       = packq(q[5], q[7]);
}

// =====================================================================
// logits256 (unchanged): 256x128 tile, in-kernel B convert, NBUF=3.
// =====================================================================
__global__ void __launch_bounds__(256, 1)
logits256(const uint32_t* __restrict__ Apack, const float* __restrict__ Bw,
          const float* __restrict__ bias, float* __restrict__ C)
{
    extern __shared__ uint32_t sm[];
    const uint32_t smb = (uint32_t)__cvta_generic_to_shared(sm);
    const int t    = threadIdx.x;
    const int lane = t & 31;
    const int wid  = t >> 5;
    const int wm   = wid & 3;
    const int wn   = wid >> 2;
    const int bn   = blockIdx.x;

    const int rb   = t >> 1;
    const int half = t & 1;
    const int bpB  = (rb >> 2) & 1;
    const int wq0  = 8 * half + 4 * (bpB ^ half);
    const int wq1  = 8 * half + 4 * ((bpB ^ 1) ^ half);

    int ng = bn * 128 + rb;
    if (ng > VOCAB - 1) ng = VOCAB - 1;
    const float* bsrc = Bw + (size_t)ng * DIM + half * 16;
    const uint32_t* srcA0 = Apack + (size_t)rb * (DIM / 2) + half * 8;
    const uint32_t* srcA1 = Apack + (size_t)(rb + 128) * (DIM / 2) + half * 8;
    const uint32_t dstA0 = (uint32_t)(rb * LP + half * 8) * 4;
    const uint32_t dstA1 = (uint32_t)((rb + 128) * LP + half * 8) * 4;

    float4 pf[4];
    auto ldB = [&](int ch) {
        const float4* p = (const float4*)(bsrc + ch * 32);
        pf[0] = p[0]; pf[1] = p[1]; pf[2] = p[2]; pf[3] = p[3];
    };
    auto stB = [&](int buf) {
        uint32_t* base = sm + buf * BUFW256 + APLANE256 + rb * LP;
        *(uint4*)(base + wq0) = packq(pf[0], pf[2]);
        *(uint4*)(base + wq1) = packq(pf[1], pf[3]);
    };
    auto issueA = [&](int ch, int buf) {
        uint32_t d = smb + (uint32_t)buf * BUFW256 * 4;
        const uint32_t* s0 = srcA0 + ch * 16;
        const uint32_t* s1 = srcA1 + ch * 16;
        CP_ASYNC16(d + dstA0, s0);
        CP_ASYNC16(d + dstA0 + 16, s0 + 4);
        CP_ASYNC16(d + dstA1, s1);
        CP_ASYNC16(d + dstA1 + 16, s1 + 4);
        CP_COMMIT();
    };

    float acc[4][8][4];
#pragma unroll
    for (int i = 0; i < 4; i++)
#pragma unroll
        for (int j = 0; j < 8; j++)
#pragma unroll
            for (int k = 0; k < 4; k++) acc[i][j][k] = 0.f;

    const int c_ = lane & 3;
    const int bt = (lane >> 4) & 1;
    const int q2 = (c_ >> 1) ^ bt;
    const int rA = wm * 64 + (lane >> 2);
    const int cB = wn * 64 + (lane >> 2);

    ldB(0);
    issueA(0, 0);
    issueA(1, 1);
    stB(0);
    ldB(1);
    CP_WAIT1();
    __syncthreads();

    const int NCH = DIM / 32;
    int bufC = 0;
    for (int ch = 0; ch < NCH; ch++) {
        const int bufN  = bufC + 1 == 3 ? 0 : bufC + 1;
        const int bufNN = bufN + 1 == 3 ? 0 : bufN + 1;
        if (ch + 1 < NCH) stB(bufN);
        if (ch + 2 < NCH) ldB(ch + 2);
        if (ch + 2 < NCH) issueA(ch + 2, bufNN);

        const uint32_t* Ab = sm + bufC * BUFW256;
        const uint32_t* Bb = Ab + APLANE256;
#pragma unroll
        for (int h = 0; h < 2; h++) {
            const int off = 8 * h + 4 * (q2 ^ h) + 2 * (c_ & 1);
            uint2 af[4][2];
#pragma unroll
            for (int mt = 0; mt < 4; mt++) {
                af[mt][0] = *(const uint2*)(Ab + (rA + 16 * mt) * LP + off);
                af[mt][1] = *(const uint2*)(Ab + (rA + 16 * mt + 8) * LP + off);
            }
#pragma unroll
            for (int nt = 0; nt < 8; nt++) {
                uint2 bf = *(const uint2*)(Bb + (cB + 8 * nt) * LP + off);
#pragma unroll
                for (int mt = 0; mt < 4; mt++)
                    mmaf16(acc[mt][nt], af[mt][0].x, af[mt][1].x,
                           af[mt][0].y, af[mt][1].y, bf.x, bf.y);
            }
        }
        CP_WAIT1();
        __syncthreads();
        bufC = bufN;
    }

    const int n0 = bn * 128 + wn * 64 + 2 * c_;
    float bz[16];
#pragma unroll
    for (int nt = 0; nt < 8; nt++) {
        int n = n0 + 8 * nt;
        bz[2 * nt]     = (n     < VOCAB) ? bias[n]     : 0.f;
        bz[2 * nt + 1] = (n + 1 < VOCAB) ? bias[n + 1] : 0.f;
    }
    const int m0 = wm * 64 + (lane >> 2);
#pragma unroll
    for (int mt = 0; mt < 4; mt++) {
        float* r0 = C + (size_t)(m0 + 16 * mt) * VOCAB;
        float* r1 = r0 + (size_t)8 * VOCAB;
#pragma unroll
        for (int nt = 0; nt < 8; nt++) {
            int n = n0 + 8 * nt;
            if (n < VOCAB) {
                r0[n] = acc[mt][nt][0] + bz[2 * nt];
                r1[n] = acc[mt][nt][2] + bz[2 * nt];
            }
            if (n + 1 < VOCAB) {
                r0[n + 1] = acc[mt][nt][1] + bz[2 * nt + 1];
                r1[n + 1] = acc[mt][nt][3] + bz[2 * nt + 1];
            }
        }
    }
}

// =====================================================================
// GRU gates from 4 split-K partials
// =====================================================================
__global__ void gru_gates(const float* __restrict__ P, size_t stride,
                          const float* __restrict__ bhh,
                          float* __restrict__ h, int ldh)
{
    int idx = blockIdx.x * blockDim.x + threadIdx.x;
    int b = idx >> 10, d = idx & 1023;
    size_t base = (size_t)b * (3 * DIM);
    float gr = 0.f, gz = 0.f, gn = 0.f;
#pragma unroll
    for (int z = 0; z < 4; z++) {
        const float* g = P + z * stride + base;
        gr += g[d];
        gz += g[DIM + d];
        gn += g[2 * DIM + d];
    }
    float r = 1.f / (1.f + expf(-(gr + bhh[d])));
    float z = 1.f / (1.f + expf(-(gz + bhh[DIM + d])));
    float n = tanhf(gn + r * bhh[2 * DIM + d]);
    h[(size_t)b * ldh + d] = (1.f - z) * n;
}

// =====================================================================
// Fused attention: h1 gates from 4 partials + online softmax.
// =====================================================================
#define ATTN_SMEM_BYTES ((1024 + 2 * 8 * 1024 + 8 + 512) * 4)

__global__ void __launch_bounds__(256)
attn_kernel(const float* __restrict__ enc, const int* __restrict__ mask,
            const float* __restrict__ P, size_t stride,
            const float* __restrict__ bhh, float* __restrict__ cat)
{
    extern __shared__ float smf[];
    float* h1s   = smf;
    float* tiles = smf + 1024;
    float* wsh   = smf + 1024 + 16384;
    int*   msk   = (int*)(smf + 1024 + 16384 + 8);

    const int b   = blockIdx.x;
    const int tid = threadIdx.x;
    const float* encb  = enc  + (size_t)b * SEQ * DIM;
    const int*   maskb = mask + b * SEQ;

    msk[tid]       = maskb[tid];
    msk[tid + 256] = maskb[tid + 256];

    {
        size_t base = (size_t)b * (3 * DIM);
        int d = tid * 4;
        float4 vr = make_float4(0.f, 0.f, 0.f, 0.f);
        float4 vz = vr, vn = vr;
#pragma unroll
        for (int z = 0; z < 4; z++) {
            const float* g = P + z * stride + base;
            float4 a = *(const float4*)(g + d);
            float4 c = *(const float4*)(g + DIM + d);
            float4 e = *(const float4*)(g + 2 * DIM + d);
            vr.x += a.x; vr.y += a.y; vr.z += a.z; vr.w += a.w;
            vz.x += c.x; vz.y += c.y; vz.z += c.z; vz.w += c.w;
            vn.x += e.x; vn.y += e.y; vn.z += e.z; vn.w += e.w;
        }
        float4 br = *(const float4*)(bhh + d);
        float4 bz = *(const float4*)(bhh + DIM + d);
        float4 bn = *(const float4*)(bhh + 2 * DIM + d);
        float h[4];
        float r0 = 1.f / (1.f + expf(-(vr.x + br.x)));
        float z0 = 1.f / (1.f + expf(-(vz.x + bz.x)));
        h[0] = (1.f - z0) * tanhf(vn.x + r0 * bn.x);
        float r1 = 1.f / (1.f + expf(-(vr.y + br.y)));
        float z1 = 1.f / (1.f + expf(-(vz.y + bz.y)));
        h[1] = (1.f - z1) * tanhf(vn.y + r1 * bn.y);
        float r2 = 1.f / (1.f + expf(-(vr.z + br.z)));
        float z2 = 1.f / (1.f + expf(-(vz.z + bz.z)));
        h[2] = (1.f - z2) * tanhf(vn.z + r2 * bn.z);
        float r3 = 1.f / (1.f + expf(-(vr.w + br.w)));
        float z3 = 1.f / (1.f + expf(-(vz.w + bz.w)));
        h[3] = (1.f - z3) * tanhf(vn.w + r3 * bn.w);
        float4 hv = make_float4(h[0], h[1], h[2], h[3]);
        *(float4*)(h1s + d) = hv;
        *(float4*)(cat + (size_t)b * (2 * DIM) + d) = hv;
    }

    const uint32_t tbase = (uint32_t)__cvta_generic_to_shared(tiles);
    auto issue = [&](int it) {
        const float* src = encb + (size_t)it * 8 * DIM + tid * 4;
        uint32_t dst = tbase + (uint32_t)((it & 1) * 32768 + tid * 16);
#pragma unroll
        for (int i = 0; i < 8; i++)
            CP_ASYNC16(dst + i * 4096, (const void*)(src + i * 1024));
    };

    issue(0); CP_COMMIT();
    issue(1); CP_COMMIT();

    float m = -1e30f, l = 0.f;
    float4 acc = make_float4(0.f, 0.f, 0.f, 0.f);

    for (int it = 0; it < SEQ / 8; it++) {
        CP_WAIT1();
        __syncthreads();
        const float* tb = tiles + (it & 1) * 8192;

        {
            int w = tid >> 5, lane = tid & 31;
            float p = 0.f;
            const float4* er = (const float4*)(tb + w * 1024);
            const float4* hr = (const float4*)h1s;
#pragma unroll
            for (int i = 0; i < 8; i++) {
                float4 e  = er[lane + i * 32];
                float4 hv = hr[lane + i * 32];
                p += e.x * hv.x + e.y * hv.y + e.z * hv.z + e.w * hv.w;
            }
#pragma unroll
            for (int off = 16; off; off >>= 1) p += __shfl_xor_sync(0xffffffffu, p, off);
            if (lane == 0) wsh[w] = msk[it * 8 + w] ? p : -1e30f;
        }
        __syncthreads();

        float wv[8];
        float tm = -1e30f;
#pragma unroll
        for (int j = 0; j < 8; j++) { wv[j] = wsh[j]; tm = fmaxf(tm, wv[j]); }
        float mnew  = fmaxf(m, tm);
        float scale = __expf(m - mnew);
        l *= scale;
        acc.x *= scale; acc.y *= scale; acc.z *= scale; acc.w *= scale;
#pragma unroll
        for (int j = 0; j < 8; j++) {
            float pj = __expf(wv[j] - mnew);
            l += pj;
            float4 e = *(const float4*)(tb + j * 1024 + tid * 4);
            acc.x += pj * e.x; acc.y += pj * e.y; acc.z += pj * e.z; acc.w += pj * e.w;
        }
        m = mnew;
        __syncthreads();

        if (it + 2 < SEQ / 8) issue(it + 2);
        CP_COMMIT();
    }

    float inv = 1.f / l;
    float4 o = make_float4(acc.x * inv, acc.y * inv, acc.z * inv, acc.w * inv);
    *(float4*)(cat + (size_t)b * (2 * DIM) + DIM + tid * 4) = o;
}

// =====================================================================
// launcher
// =====================================================================
extern "C" void kernel_launch(void* const* d_in, const int* in_sizes, int n_in,
                              void* d_out, int out_size)
{
    (void)in_sizes; (void)n_in; (void)out_size;
    const int*   tokens   = (const int*)  d_in[0];
    const float* enc      = (const float*)d_in[1];
    const int*   encmask  = (const int*)  d_in[2];
    const float* dec_emb  = (const float*)d_in[3];
    const float* Wih0     = (const float*)d_in[4];
    const float* bih0     = (const float*)d_in[6];
    const float* bhh0     = (const float*)d_in[7];
    const float* Wih1     = (const float*)d_in[8];
    const float* bih1     = (const float*)d_in[10];
    const float* bhh1     = (const float*)d_in[11];
    const float* preout_w = (const float*)d_in[12];
    const float* preout_b = (const float*)d_in[13];
    const float* out_w    = (const float*)d_in[14];
    const float* out_b    = (const float*)d_in[15];
    float* logits = (float*)d_out;

    float *giP, *h0, *cat, *preP;
    uint32_t *apack, *w0p, *w1p, *prep;
    cudaGetSymbolAddress((void**)&giP,   g_giP);
    cudaGetSymbolAddress((void**)&h0,    g_h0);
    cudaGetSymbolAddress((void**)&cat,   g_cat);
    cudaGetSymbolAddress((void**)&preP,  g_preP);
    cudaGetSymbolAddress((void**)&apack, g_Apack);
    cudaGetSymbolAddress((void**)&w0p,   g_Wih0p);
    cudaGetSymbolAddress((void**)&w1p,   g_Wih1p);
    cudaGetSymbolAddress((void**)&prep,  g_Prep);

    const size_t GI_STRIDE  = (size_t)BATCH * 3 * DIM;
    const size_t PRE_STRIDE = (size_t)BATCH * DIM;

    static int smem_set = 0;
    if (!smem_set) {
        cudaFuncSetAttribute(logits256, cudaFuncAttributeMaxDynamicSharedMemorySize, LG256_SMEM_BYTES);
        cudaFuncSetAttribute(gemm_f16, cudaFuncAttributeMaxDynamicSharedMemorySize, GM_SMEM_BYTES);
        cudaFuncSetAttribute(attn_kernel, cudaFuncAttributeMaxDynamicSharedMemorySize, ATTN_SMEM_BYTES);
        smem_set = 1;
    }

    // 0) fused weight prepack (w0p / w1p / prep)
    prepack_all<<<1024, 256>>>(Wih0, Wih1, preout_w, w0p, w1p, prep);

    // 1) gi0 split-K z=4 (z=0 carries bias)
    gemm_f16<<<dim3(2 * (3 * DIM / 128), 1, 4), 256, GM_SMEM_BYTES>>>(
        3 * DIM, DIM / 4, DIM / 2, dec_emb, DIM, tokens, w0p, bih0,
        giP, 3 * DIM, GI_STRIDE);

    // 2) h0 = gates(sum of 4 partials)
    gru_gates<<<(BATCH * DIM) / 256, 256>>>(giP, GI_STRIDE, bhh0, h0, DIM);

    // 3) gi1 split-K z=4
    gemm_f16<<<dim3(2 * (3 * DIM / 128), 1, 4), 256, GM_SMEM_BYTES>>>(
        3 * DIM, DIM / 4, DIM / 2, h0, DIM, nullptr, w1p, bih1,
        giP, 3 * DIM, GI_STRIDE);

    // 4) fused: h1 gates (4 partials) + attention summary -> cat
    attn_kernel<<<BATCH, 256, ATTN_SMEM_BYTES>>>(enc, encmask, giP, GI_STRIDE, bhh1, cat);

    // 5) preout split-K z=4 (z=0 carries bias)
    gemm_f16<<<dim3(2 * (DIM / 128), 1, 4), 256, GM_SMEM_BYTES>>>(
        DIM, 2 * DIM / 4, DIM, cat, 2 * DIM, nullptr, prep, preout_b,
        preP, DIM, PRE_STRIDE);

    // 6) celu(sum of 4 partials) + fp16 pack -> g_Apack
    prepack_combine<<<32, 256>>>(preP, PRE_STRIDE, apack);

    // 7) logits = Apack @ out_w^T + out_b
    logits256<<<VPAD / 128, 256, LG256_SMEM_BYTES>>>(apack, out_w, out_b, logits);
}